// round 10
// baseline (speedup 1.0000x reference)
#include <cuda_runtime.h>
#include <cuda_bf16.h>
#include <stdint.h>

typedef unsigned long long u64;

// Problem constants (fixed shapes for this problem)
#define MAXN 100000
#define MAXE 800000
#define DIM  128
#define LD   136   // padded SMEM row stride in bf16 (272B: 16B-aligned, ldmatrix conflict-free)

// Scratch (device globals — no allocation allowed)
__device__ float         g_h[(size_t)MAXN * DIM];      // activations (layer1 out)
__device__ float         g_h2[(size_t)MAXN * DIM];     // activations (layer2 out)
__device__ __nv_bfloat16 g_whi[3 * DIM * DIM];         // W1/W2/W3 hi
__device__ __nv_bfloat16 g_wlo[3 * DIM * DIM];         // W1/W2/W3 lo
__device__ float g_rdeg[MAXN];
__device__ int   g_row[MAXE];
__device__ int   g_col[MAXE];
__device__ int   g_cnt[MAXN];
__device__ int   g_offs[MAXN];
__device__ int   g_cursor[MAXN];
__device__ int   g_srcs[MAXE];
__device__ int   g_bsum[1024];
__device__ int   g_is32;   // monotone under atomicOr; input-fixed -> never re-zeroed

__device__ __forceinline__ uint32_t smem_u32(const void* p) {
    uint32_t a;
    asm("{ .reg .u64 t; cvta.to.shared.u64 t, %1; cvt.u32.u64 %0, t; }" : "=r"(a) : "l"(p));
    return a;
}

// ---------------------------------------------------------------------------
// Fused: zero cnt[] + dtype probe. Probe: int64 values < 2^31 have zero high
// words; int32 probed words are random indices (mostly nonzero).
// ---------------------------------------------------------------------------
__global__ void zero_probe_kernel(const unsigned* __restrict__ w, int E,
                                  int* __restrict__ cnt, int n,
                                  int* __restrict__ flag) {
    int i = blockIdx.x * blockDim.x + threadIdx.x;
    if (i < n) cnt[i] = 0;
    if (i < E) {
        if (w[2 * i + 1] != 0u) atomicOr(flag, 1);
    }
}

__global__ void convert_count_kernel(const void* __restrict__ ei,
                                     int* __restrict__ row, int* __restrict__ col,
                                     int* __restrict__ cnt,
                                     int E, const int* __restrict__ flag) {
    int i = blockIdx.x * blockDim.x + threadIdx.x;
    if (i >= E) return;
    int r, c;
    if (*flag) {
        const int* p = (const int*)ei;
        r = p[i];
        c = p[E + i];
    } else {
        const long long* p = (const long long*)ei;
        r = (int)p[i];
        c = (int)p[E + i];
    }
    row[i] = r;
    col[i] = c;
    atomicAdd(&cnt[r], 1);
}

__global__ void scan1_kernel(const int* __restrict__ cnt, int* __restrict__ offs,
                             int* __restrict__ bsum, int n) {
    __shared__ int sh[1024];
    int i = blockIdx.x * 1024 + threadIdx.x;
    int v = (i < n) ? cnt[i] : 0;
    sh[threadIdx.x] = v;
    __syncthreads();
    #pragma unroll
    for (int d = 1; d < 1024; d <<= 1) {
        int t = (threadIdx.x >= d) ? sh[threadIdx.x - d] : 0;
        __syncthreads();
        sh[threadIdx.x] += t;
        __syncthreads();
    }
    if (i < n) offs[i] = sh[threadIdx.x] - v;
    if (threadIdx.x == 1023) bsum[blockIdx.x] = sh[1023];
}

__global__ void scan2_kernel(int* __restrict__ bsum, int nb) {
    __shared__ int sh[1024];
    int v = (threadIdx.x < nb) ? bsum[threadIdx.x] : 0;
    sh[threadIdx.x] = v;
    __syncthreads();
    #pragma unroll
    for (int d = 1; d < 1024; d <<= 1) {
        int t = (threadIdx.x >= d) ? sh[threadIdx.x - d] : 0;
        __syncthreads();
        sh[threadIdx.x] += t;
        __syncthreads();
    }
    if (threadIdx.x < nb) bsum[threadIdx.x] = sh[threadIdx.x] - v;
}

__global__ void scan3_kernel(int* __restrict__ offs, const int* __restrict__ bsum,
                             const int* __restrict__ cnt, int* __restrict__ cursor,
                             float* __restrict__ rdeg, int n) {
    int i = blockIdx.x * blockDim.x + threadIdx.x;
    if (i >= n) return;
    int o = offs[i] + bsum[i >> 10];
    offs[i] = o;
    cursor[i] = o;
    rdeg[i] = 1.0f / fmaxf((float)cnt[i], 1.0f);
}

__global__ void fill_kernel(const int* __restrict__ row, const int* __restrict__ col,
                            int* __restrict__ cursor, int* __restrict__ srcs, int E) {
    int e = blockIdx.x * blockDim.x + threadIdx.x;
    if (e >= E) return;
    int idx = atomicAdd(&cursor[row[e]], 1);
    srcs[idx] = col[e];
}

// ---------------------------------------------------------------------------
// fp32 -> split bf16 (hi + lo)
// ---------------------------------------------------------------------------
__device__ __forceinline__ void split2(float a, float b,
                                       __nv_bfloat162& hi, __nv_bfloat162& lo) {
    __nv_bfloat16 ha = __float2bfloat16_rn(a);
    __nv_bfloat16 hb = __float2bfloat16_rn(b);
    hi = __nv_bfloat162(ha, hb);
    lo = __floats2bfloat162_rn(a - __bfloat162float(ha), b - __bfloat162float(hb));
}

__global__ void split_w_kernel(const float4* __restrict__ W1,
                               const float4* __restrict__ W2,
                               const float4* __restrict__ W3,
                               __nv_bfloat162* __restrict__ whi,
                               __nv_bfloat162* __restrict__ wlo) {
    int i = blockIdx.x * blockDim.x + threadIdx.x;   // over 3*4096 float4s
    if (i >= 3 * 4096) return;
    int layer = i / 4096, j = i % 4096;
    const float4* W = (layer == 0) ? W1 : (layer == 1) ? W2 : W3;
    float4 v = __ldg(W + j);
    __nv_bfloat162 h0, l0, h1, l1;
    split2(v.x, v.y, h0, l0);
    split2(v.z, v.w, h1, l1);
    whi[2 * i] = h0;  whi[2 * i + 1] = h1;
    wlo[2 * i] = l0;  wlo[2 * i + 1] = l1;
}

// ---------------------------------------------------------------------------
// Tensor-core split-bf16 GEMM via mma.sync (HMMA pipe):
//   out[M,128] = A[M,128] @ W[128,128]^T + bias
//   D = Ahi@Whi + Ahi@Wlo + Alo@Whi  (3 sequential passes, fp32 acc)
// CTA: 128x128, 16 warps (512 threads) in 4x4 grid; warp = 32x32 via
// 2x4 m16n8k16 tiles.
//
// A-staging modes:
//   AGG=false: A = fp32 matrix (layer 1's x); split hi/lo inline.
//   AGG=true : A = relu(mean of in-neighbors of hsrc) computed IN-CTA from
//              CSR (fused message passing; no global intermediate). The
//              layer's OUTPUT must not alias hsrc (ping-pong buffers).
// ---------------------------------------------------------------------------
#define SMEM_TILE (128 * LD)                 // bf16 elements per tile
#define SMEM_GEMM_BYTES (4 * SMEM_TILE * 2)  // 139,264 B

template <bool AGG>
__global__ __launch_bounds__(512, 1) void tc_gemm_kernel(
    const float* __restrict__ Asrc,          // AGG ? hsrc : x
    const int* __restrict__ offs,
    const int* __restrict__ cnt,
    const int* __restrict__ srcs,
    const float* __restrict__ rdeg,
    const __nv_bfloat16* __restrict__ Whi,
    const __nv_bfloat16* __restrict__ Wlo,
    const float* __restrict__ bias,
    float* __restrict__ out,
    int M)
{
    extern __shared__ __nv_bfloat16 sm[];
    const int tid  = threadIdx.x;
    const int wid  = tid >> 5;
    const int lane = tid & 31;
    const int m0   = blockIdx.x * 128;

    __nv_bfloat16* sAhi = sm;
    __nv_bfloat16* sAlo = sAhi + SMEM_TILE;
    __nv_bfloat16* sWhi = sAlo + SMEM_TILE;
    __nv_bfloat16* sWlo = sWhi + SMEM_TILE;

    // ---- stage W tiles (both layers' hi/lo; 128 rows x 16 chunks) ----
    for (int idx = tid; idx < 2048; idx += 512) {
        int r  = idx >> 4;
        int ck = idx & 15;
        uint4 wa = __ldg((const uint4*)(Whi + (size_t)r * DIM) + ck);
        uint4 wb = __ldg((const uint4*)(Wlo + (size_t)r * DIM) + ck);
        *(uint4*)(sWhi + r * LD + ck * 8) = wa;
        *(uint4*)(sWlo + r * LD + ck * 8) = wb;
    }

    // ---- stage A tiles ----
    if (AGG) {
        // Fused message passing: warp w handles rows w*8 .. w*8+7.
        // Lane owns a 16B chunk (4 floats) of the 512B row.
        #pragma unroll 1
        for (int i = 0; i < 8; ++i) {
            int r = wid * 8 + i;
            int node = m0 + r;
            float4 acc = make_float4(0.f, 0.f, 0.f, 0.f);
            if (node < M) {
                int start = __ldg(offs + node);
                int c     = __ldg(cnt + node);
                int j = 0;
                for (; j + 4 <= c; j += 4) {
                    int s0 = __ldg(srcs + start + j);
                    int s1 = __ldg(srcs + start + j + 1);
                    int s2 = __ldg(srcs + start + j + 2);
                    int s3 = __ldg(srcs + start + j + 3);
                    float4 v0 = __ldg((const float4*)(Asrc + (size_t)s0 * DIM) + lane);
                    float4 v1 = __ldg((const float4*)(Asrc + (size_t)s1 * DIM) + lane);
                    float4 v2 = __ldg((const float4*)(Asrc + (size_t)s2 * DIM) + lane);
                    float4 v3 = __ldg((const float4*)(Asrc + (size_t)s3 * DIM) + lane);
                    acc.x += (v0.x + v1.x) + (v2.x + v3.x);
                    acc.y += (v0.y + v1.y) + (v2.y + v3.y);
                    acc.z += (v0.z + v1.z) + (v2.z + v3.z);
                    acc.w += (v0.w + v1.w) + (v2.w + v3.w);
                }
                for (; j < c; ++j) {
                    int s0 = __ldg(srcs + start + j);
                    float4 v0 = __ldg((const float4*)(Asrc + (size_t)s0 * DIM) + lane);
                    acc.x += v0.x;
                    acc.y += v0.y;
                    acc.z += v0.z;
                    acc.w += v0.w;
                }
                float rd = __ldg(rdeg + node);
                acc.x = fmaxf(acc.x * rd, 0.f);
                acc.y = fmaxf(acc.y * rd, 0.f);
                acc.z = fmaxf(acc.z * rd, 0.f);
                acc.w = fmaxf(acc.w * rd, 0.f);
            }
            __nv_bfloat162 h0, l0, h1, l1;
            split2(acc.x, acc.y, h0, l0);
            split2(acc.z, acc.w, h1, l1);
            *(uint2*)(sAhi + r * LD + lane * 4) =
                make_uint2(*(uint32_t*)&h0, *(uint32_t*)&h1);
            *(uint2*)(sAlo + r * LD + lane * 4) =
                make_uint2(*(uint32_t*)&l0, *(uint32_t*)&l1);
        }
    } else {
        // Layer 1: read fp32 x, split inline.
        for (int idx = tid; idx < 2048; idx += 512) {
            int r  = idx >> 4;
            int ck = idx & 15;
            int m  = m0 + r;
            uint4 hi4 = make_uint4(0, 0, 0, 0), lo4 = hi4;
            if (m < M) {
                float4 va = __ldg((const float4*)(Asrc + (size_t)m * DIM + ck * 8));
                float4 vb = __ldg((const float4*)(Asrc + (size_t)m * DIM + ck * 8) + 1);
                __nv_bfloat162 h0, l0, h1, l1, h2, l2, h3, l3;
                split2(va.x, va.y, h0, l0);
                split2(va.z, va.w, h1, l1);
                split2(vb.x, vb.y, h2, l2);
                split2(vb.z, vb.w, h3, l3);
                hi4 = make_uint4(*(uint32_t*)&h0, *(uint32_t*)&h1,
                                 *(uint32_t*)&h2, *(uint32_t*)&h3);
                lo4 = make_uint4(*(uint32_t*)&l0, *(uint32_t*)&l1,
                                 *(uint32_t*)&l2, *(uint32_t*)&l3);
            }
            *(uint4*)(sAhi + r * LD + ck * 8) = hi4;
            *(uint4*)(sAlo + r * LD + ck * 8) = lo4;
        }
    }
    __syncthreads();

    const int mw = wid >> 2;          // 0..3
    const int nw = wid & 3;           // 0..3
    const int mBase = mw * 32;
    const int nBase = nw * 32;

    float acc[2][4][4];
    #pragma unroll
    for (int i = 0; i < 2; ++i)
        #pragma unroll
        for (int j = 0; j < 4; ++j)
            #pragma unroll
            for (int q = 0; q < 4; ++q) acc[i][j][q] = 0.f;

    // ldmatrix per-lane source addresses (byte offsets inside a tile)
    const uint32_t aRowOff = (uint32_t)(mBase + (lane & 15)) * (LD * 2) + ((lane >> 4) << 4);
    const uint32_t bRowOff = (uint32_t)(nBase + (lane & 7)) * (LD * 2) + (((lane >> 3) & 1) << 4);

    const uint32_t sb     = smem_u32(sm);
    const uint32_t offAhi = 0;
    const uint32_t offAlo = SMEM_TILE * 2;
    const uint32_t offWhi = SMEM_TILE * 4;
    const uint32_t offWlo = SMEM_TILE * 6;

    #pragma unroll 1
    for (int pass = 0; pass < 3; ++pass) {
        const uint32_t aBase = sb + ((pass == 2) ? offAlo : offAhi) + aRowOff;
        const uint32_t bBase = sb + ((pass == 1) ? offWlo : offWhi) + bRowOff;

        #pragma unroll 1
        for (int k = 0; k < 8; ++k) {          // k16 steps, +32B each
            uint32_t a[2][4];
            #pragma unroll
            for (int mt = 0; mt < 2; ++mt) {
                uint32_t addr = aBase + (uint32_t)(mt * 16) * (LD * 2) + k * 32;
                asm volatile("ldmatrix.sync.aligned.m8n8.x4.shared.b16 {%0,%1,%2,%3}, [%4];"
                             : "=r"(a[mt][0]), "=r"(a[mt][1]), "=r"(a[mt][2]), "=r"(a[mt][3])
                             : "r"(addr));
            }
            uint32_t b[4][2];
            #pragma unroll
            for (int nt = 0; nt < 4; ++nt) {
                uint32_t addr = bBase + (uint32_t)(nt * 8) * (LD * 2) + k * 32;
                asm volatile("ldmatrix.sync.aligned.m8n8.x2.shared.b16 {%0,%1}, [%2];"
                             : "=r"(b[nt][0]), "=r"(b[nt][1])
                             : "r"(addr));
            }
            #pragma unroll
            for (int mt = 0; mt < 2; ++mt)
                #pragma unroll
                for (int nt = 0; nt < 4; ++nt) {
                    asm volatile(
                        "mma.sync.aligned.m16n8k16.row.col.f32.bf16.bf16.f32 "
                        "{%0,%1,%2,%3}, {%4,%5,%6,%7}, {%8,%9}, {%0,%1,%2,%3};"
                        : "+f"(acc[mt][nt][0]), "+f"(acc[mt][nt][1]),
                          "+f"(acc[mt][nt][2]), "+f"(acc[mt][nt][3])
                        : "r"(a[mt][0]), "r"(a[mt][1]), "r"(a[mt][2]), "r"(a[mt][3]),
                          "r"(b[nt][0]), "r"(b[nt][1]));
                }
        }
    }

    // ---- epilogue: + bias, fp32 store ----
    const int r0 = lane >> 2;           // 0..7
    const int c0 = (lane & 3) * 2;      // 0,2,4,6
    #pragma unroll
    for (int nt = 0; nt < 4; ++nt) {
        int coln = nBase + nt * 8 + c0;
        float2 bv = __ldg((const float2*)(bias + coln));
        #pragma unroll
        for (int mt = 0; mt < 2; ++mt) {
            int row = m0 + mBase + mt * 16 + r0;
            if (row < M) {
                float2 v0 = make_float2(acc[mt][nt][0] + bv.x, acc[mt][nt][1] + bv.y);
                *(float2*)(out + (size_t)row * DIM + coln) = v0;
            }
            if (row + 8 < M) {
                float2 v1 = make_float2(acc[mt][nt][2] + bv.x, acc[mt][nt][3] + bv.y);
                *(float2*)(out + (size_t)(row + 8) * DIM + coln) = v1;
            }
        }
    }
}

// ---------------------------------------------------------------------------
// kernel_launch
// ---------------------------------------------------------------------------
extern "C" void kernel_launch(void* const* d_in, const int* in_sizes, int n_in,
                              void* d_out, int out_size)
{
    const float* x   = (const float*)d_in[0];
    const void*  ei  = d_in[1];
    const float* W1  = (const float*)d_in[2];
    const float* b1  = (const float*)d_in[3];
    const float* W2  = (const float*)d_in[4];
    const float* b2  = (const float*)d_in[5];
    const float* W3  = (const float*)d_in[6];
    const float* b3  = (const float*)d_in[7];
    float*       out = (float*)d_out;

    const int N = in_sizes[0] / DIM;
    const int E = in_sizes[1] / 2;

    float* h;             cudaGetSymbolAddress((void**)&h,      g_h);
    float* h2;            cudaGetSymbolAddress((void**)&h2,     g_h2);
    __nv_bfloat16* whi;   cudaGetSymbolAddress((void**)&whi,    g_whi);
    __nv_bfloat16* wlo;   cudaGetSymbolAddress((void**)&wlo,    g_wlo);
    float* rdeg;          cudaGetSymbolAddress((void**)&rdeg,   g_rdeg);
    int*   row;           cudaGetSymbolAddress((void**)&row,    g_row);
    int*   col;           cudaGetSymbolAddress((void**)&col,    g_col);
    int*   cnt;           cudaGetSymbolAddress((void**)&cnt,    g_cnt);
    int*   offs;          cudaGetSymbolAddress((void**)&offs,   g_offs);
    int*   cursor;        cudaGetSymbolAddress((void**)&cursor, g_cursor);
    int*   srcs;          cudaGetSymbolAddress((void**)&srcs,   g_srcs);
    int*   bsum;          cudaGetSymbolAddress((void**)&bsum,   g_bsum);
    int*   flag;          cudaGetSymbolAddress((void**)&flag,   g_is32);

    const int egrid = (E + 255) / 256;
    const int ngrid = (N + 255) / 256;
    const int nb    = (N + 1023) / 1024;
    const int ggrid = (N + 127) / 128;

    cudaFuncSetAttribute(tc_gemm_kernel<true>,
                         cudaFuncAttributeMaxDynamicSharedMemorySize, SMEM_GEMM_BYTES);
    cudaFuncSetAttribute(tc_gemm_kernel<false>,
                         cudaFuncAttributeMaxDynamicSharedMemorySize, SMEM_GEMM_BYTES);

    // 0) zero cnt + dtype probe, then normalize edge indices + count in-degrees
    zero_probe_kernel<<<egrid, 256>>>((const unsigned*)ei, E, cnt, N, flag);
    convert_count_kernel<<<egrid, 256>>>(ei, row, col, cnt, E, flag);

    // 1) CSR build
    scan1_kernel<<<nb, 1024>>>(cnt, offs, bsum, N);
    scan2_kernel<<<1, 1024>>>(bsum, nb);
    scan3_kernel<<<ngrid, 256>>>(offs, bsum, cnt, cursor, rdeg, N);
    fill_kernel<<<egrid, 256>>>(row, col, cursor, srcs, E);

    // 2) split weights (tiny)
    split_w_kernel<<<(3 * 4096 + 255) / 256, 256>>>(
        (const float4*)W1, (const float4*)W2, (const float4*)W3,
        (__nv_bfloat162*)whi, (__nv_bfloat162*)wlo);

    // 3) layer 1: h = x @ W1^T + b1   (fp32 x split inline during staging)
    tc_gemm_kernel<false><<<ggrid, 512, SMEM_GEMM_BYTES>>>(
        x, nullptr, nullptr, nullptr, nullptr, whi, wlo, b1, h, N);

    // 4) layer 2 (fused mp): h2 = relu(mean_nbrs(h)) @ W2^T + b2
    tc_gemm_kernel<true><<<ggrid, 512, SMEM_GEMM_BYTES>>>(
        h, offs, cnt, srcs, rdeg, whi + DIM * DIM, wlo + DIM * DIM, b2, h2, N);

    // 5) layer 3 (fused mp): out = relu(mean_nbrs(h2)) @ W3^T + b3
    tc_gemm_kernel<true><<<ggrid, 512, SMEM_GEMM_BYTES>>>(
        h2, offs, cnt, srcs, rdeg, whi + 2 * DIM * DIM, wlo + 2 * DIM * DIM, b3, out, N);
}

// round 11
// speedup vs baseline: 1.1659x; 1.1659x over previous
#include <cuda_runtime.h>
#include <cuda_bf16.h>
#include <stdint.h>

typedef unsigned long long u64;

// Problem constants (fixed shapes for this problem)
#define MAXN 100000
#define MAXE 800000
#define DIM  128
#define LD   136   // padded SMEM row stride in bf16 (272B: 16B-aligned, ldmatrix conflict-free)

// Scratch (device globals — no allocation allowed)
__device__ float         g_h[(size_t)MAXN * DIM];      // fp32 activations (GEMM out)
__device__ __nv_bfloat16 g_ahi[(size_t)MAXN * DIM];    // split-bf16 GEMM input (hi)
__device__ __nv_bfloat16 g_alo[(size_t)MAXN * DIM];    // split-bf16 GEMM input (lo)
__device__ __nv_bfloat16 g_whi[3 * DIM * DIM];         // W1/W2/W3 hi
__device__ __nv_bfloat16 g_wlo[3 * DIM * DIM];         // W1/W2/W3 lo
__device__ float g_rdeg[MAXN];
__device__ int   g_row[MAXE];
__device__ int   g_col[MAXE];
__device__ int   g_cnt[MAXN];
__device__ int   g_offs[MAXN];
__device__ int   g_cursor[MAXN];
__device__ int   g_srcs[MAXE];
__device__ int   g_bsum[1024];
__device__ int   g_is32;   // monotone under atomicOr; input-fixed -> never re-zeroed

__device__ __forceinline__ uint32_t smem_u32(const void* p) {
    uint32_t a;
    asm("{ .reg .u64 t; cvta.to.shared.u64 t, %1; cvt.u32.u64 %0, t; }" : "=r"(a) : "l"(p));
    return a;
}

// ---------------------------------------------------------------------------
// fp32 -> split bf16 (hi + lo)
// ---------------------------------------------------------------------------
__device__ __forceinline__ void split2(float a, float b,
                                       __nv_bfloat162& hi, __nv_bfloat162& lo) {
    __nv_bfloat16 ha = __float2bfloat16_rn(a);
    __nv_bfloat16 hb = __float2bfloat16_rn(b);
    hi = __nv_bfloat162(ha, hb);
    lo = __floats2bfloat162_rn(a - __bfloat162float(ha), b - __bfloat162float(hb));
}

// ---------------------------------------------------------------------------
// Fused: zero cnt[] + dtype probe + weight split (all independent).
// Probe: int64 values < 2^31 have zero high words; int32 probed words are
// random indices (mostly nonzero).
// ---------------------------------------------------------------------------
__global__ void zero_probe_splitw_kernel(
    const unsigned* __restrict__ w, int E,
    int* __restrict__ cnt, int n,
    int* __restrict__ flag,
    const float4* __restrict__ W1, const float4* __restrict__ W2,
    const float4* __restrict__ W3,
    __nv_bfloat162* __restrict__ whi, __nv_bfloat162* __restrict__ wlo)
{
    int i = blockIdx.x * blockDim.x + threadIdx.x;
    if (i < n) cnt[i] = 0;
    if (i < E) {
        if (w[2 * i + 1] != 0u) atomicOr(flag, 1);
    }
    if (i < 3 * 4096) {
        int layer = i / 4096, j = i % 4096;
        const float4* W = (layer == 0) ? W1 : (layer == 1) ? W2 : W3;
        float4 v = __ldg(W + j);
        __nv_bfloat162 h0, l0, h1, l1;
        split2(v.x, v.y, h0, l0);
        split2(v.z, v.w, h1, l1);
        whi[2 * i] = h0;  whi[2 * i + 1] = h1;
        wlo[2 * i] = l0;  wlo[2 * i + 1] = l1;
    }
}

__global__ void convert_count_kernel(const void* __restrict__ ei,
                                     int* __restrict__ row, int* __restrict__ col,
                                     int* __restrict__ cnt,
                                     int E, const int* __restrict__ flag) {
    int i = blockIdx.x * blockDim.x + threadIdx.x;
    if (i >= E) return;
    int r, c;
    if (*flag) {
        const int* p = (const int*)ei;
        r = p[i];
        c = p[E + i];
    } else {
        const long long* p = (const long long*)ei;
        r = (int)p[i];
        c = (int)p[E + i];
    }
    row[i] = r;
    col[i] = c;
    atomicAdd(&cnt[r], 1);
}

__global__ void scan1_kernel(const int* __restrict__ cnt, int* __restrict__ offs,
                             int* __restrict__ bsum, int n) {
    __shared__ int sh[1024];
    int i = blockIdx.x * 1024 + threadIdx.x;
    int v = (i < n) ? cnt[i] : 0;
    sh[threadIdx.x] = v;
    __syncthreads();
    #pragma unroll
    for (int d = 1; d < 1024; d <<= 1) {
        int t = (threadIdx.x >= d) ? sh[threadIdx.x - d] : 0;
        __syncthreads();
        sh[threadIdx.x] += t;
        __syncthreads();
    }
    if (i < n) offs[i] = sh[threadIdx.x] - v;
    if (threadIdx.x == 1023) bsum[blockIdx.x] = sh[1023];
}

__global__ void scan2_kernel(int* __restrict__ bsum, int nb) {
    __shared__ int sh[1024];
    int v = (threadIdx.x < nb) ? bsum[threadIdx.x] : 0;
    sh[threadIdx.x] = v;
    __syncthreads();
    #pragma unroll
    for (int d = 1; d < 1024; d <<= 1) {
        int t = (threadIdx.x >= d) ? sh[threadIdx.x - d] : 0;
        __syncthreads();
        sh[threadIdx.x] += t;
        __syncthreads();
    }
    if (threadIdx.x < nb) bsum[threadIdx.x] = sh[threadIdx.x] - v;
}

__global__ void scan3_kernel(int* __restrict__ offs, const int* __restrict__ bsum,
                             const int* __restrict__ cnt, int* __restrict__ cursor,
                             float* __restrict__ rdeg, int n) {
    int i = blockIdx.x * blockDim.x + threadIdx.x;
    if (i >= n) return;
    int o = offs[i] + bsum[i >> 10];
    offs[i] = o;
    cursor[i] = o;
    rdeg[i] = 1.0f / fmaxf((float)cnt[i], 1.0f);
}

__global__ void fill_kernel(const int* __restrict__ row, const int* __restrict__ col,
                            int* __restrict__ cursor, int* __restrict__ srcs, int E) {
    int e = blockIdx.x * blockDim.x + threadIdx.x;
    if (e >= E) return;
    int idx = atomicAdd(&cursor[row[e]], 1);
    srcs[idx] = col[e];
}

// ---------------------------------------------------------------------------
// Pull-mode aggregate: relu(mean of in-neighbors) -> split bf16 (hi, lo)
// One warp per node; lane owns 4 floats. Unrolled x4 for MLP.
// ---------------------------------------------------------------------------
__global__ __launch_bounds__(256) void aggregate_kernel(
    const float* __restrict__ h,
    const int* __restrict__ offs,
    const int* __restrict__ cnt,
    const int* __restrict__ srcs,
    const float* __restrict__ rdeg,
    __nv_bfloat162* __restrict__ ahi,
    __nv_bfloat162* __restrict__ alo,
    int N)
{
    int node = blockIdx.x * 8 + (threadIdx.x >> 5);
    if (node >= N) return;
    int lane = threadIdx.x & 31;

    int start = __ldg(offs + node);
    int c     = __ldg(cnt + node);

    float4 acc = make_float4(0.f, 0.f, 0.f, 0.f);
    int j = 0;
    for (; j + 4 <= c; j += 4) {
        int s0 = __ldg(srcs + start + j);
        int s1 = __ldg(srcs + start + j + 1);
        int s2 = __ldg(srcs + start + j + 2);
        int s3 = __ldg(srcs + start + j + 3);
        float4 v0 = __ldg((const float4*)(h + (size_t)s0 * DIM) + lane);
        float4 v1 = __ldg((const float4*)(h + (size_t)s1 * DIM) + lane);
        float4 v2 = __ldg((const float4*)(h + (size_t)s2 * DIM) + lane);
        float4 v3 = __ldg((const float4*)(h + (size_t)s3 * DIM) + lane);
        acc.x += (v0.x + v1.x) + (v2.x + v3.x);
        acc.y += (v0.y + v1.y) + (v2.y + v3.y);
        acc.z += (v0.z + v1.z) + (v2.z + v3.z);
        acc.w += (v0.w + v1.w) + (v2.w + v3.w);
    }
    for (; j < c; ++j) {
        int s0 = __ldg(srcs + start + j);
        float4 v0 = __ldg((const float4*)(h + (size_t)s0 * DIM) + lane);
        acc.x += v0.x;
        acc.y += v0.y;
        acc.z += v0.z;
        acc.w += v0.w;
    }

    float rd = __ldg(rdeg + node);
    float4 o;
    o.x = fmaxf(acc.x * rd, 0.f);
    o.y = fmaxf(acc.y * rd, 0.f);
    o.z = fmaxf(acc.z * rd, 0.f);
    o.w = fmaxf(acc.w * rd, 0.f);

    __nv_bfloat162 h0, l0, h1, l1;
    split2(o.x, o.y, h0, l0);
    split2(o.z, o.w, h1, l1);
    size_t base = (size_t)node * (DIM / 2) + lane * 2;
    ahi[base] = h0;  ahi[base + 1] = h1;
    alo[base] = l0;  alo[base + 1] = l1;
}

// ---------------------------------------------------------------------------
// Tensor-core split-bf16 GEMM via mma.sync (HMMA pipe):
//   out[M,128] = A[M,128] @ W[128,128]^T + bias
//   D = Ahi@Whi + Ahi@Wlo + Alo@Whi  (3 sequential passes, fp32 acc)
// CTA: 64x128 (BM=64 -> 102KB SMEM -> 2 CTAs/SM for cross-CTA overlap of
// staging and MMA), 16 warps (512 threads) in 4x4 grid; warp = 16x32 via
// 1x4 m16n8k16 tiles.
// CONVERT=true: A source is fp32 (layer 1's x); split hi/lo during staging.
// ---------------------------------------------------------------------------
#define BM 64
#define A_TILE (BM * LD)                     // bf16 elements per A tile
#define W_TILE (128 * LD)                    // bf16 elements per W tile
#define SMEM_GEMM_BYTES ((2 * A_TILE + 2 * W_TILE) * 2)   // 104,448 B

template <bool CONVERT>
__global__ __launch_bounds__(512, 2) void tc_gemm_kernel(
    const void* __restrict__ Asrc,           // CONVERT ? fp32[M,128] : bf16 hi
    const __nv_bfloat16* __restrict__ Alo,   // used when !CONVERT
    const __nv_bfloat16* __restrict__ Whi,
    const __nv_bfloat16* __restrict__ Wlo,
    const float* __restrict__ bias,
    float* __restrict__ out,
    int M)
{
    extern __shared__ __nv_bfloat16 sm[];
    const int tid  = threadIdx.x;
    const int wid  = tid >> 5;
    const int lane = tid & 31;
    const int m0   = blockIdx.x * BM;

    __nv_bfloat16* sAhi = sm;
    __nv_bfloat16* sAlo = sAhi + A_TILE;
    __nv_bfloat16* sWhi = sAlo + A_TILE;
    __nv_bfloat16* sWlo = sWhi + W_TILE;

    // ---- stage A tiles (64 rows x 16 chunks = 1024 items; 2 iters) ----
    for (int idx = tid; idx < BM * 16; idx += 512) {
        int r  = idx >> 4;      // row 0..63
        int ck = idx & 15;      // chunk of 8 bf16 (16B)
        int m  = m0 + r;
        if (CONVERT) {
            const float* x = (const float*)Asrc;
            uint4 hi4 = make_uint4(0, 0, 0, 0), lo4 = hi4;
            if (m < M) {
                float4 va = __ldg((const float4*)(x + (size_t)m * DIM + ck * 8));
                float4 vb = __ldg((const float4*)(x + (size_t)m * DIM + ck * 8) + 1);
                __nv_bfloat162 h0, l0, h1, l1, h2, l2, h3, l3;
                split2(va.x, va.y, h0, l0);
                split2(va.z, va.w, h1, l1);
                split2(vb.x, vb.y, h2, l2);
                split2(vb.z, vb.w, h3, l3);
                hi4 = make_uint4(*(uint32_t*)&h0, *(uint32_t*)&h1,
                                 *(uint32_t*)&h2, *(uint32_t*)&h3);
                lo4 = make_uint4(*(uint32_t*)&l0, *(uint32_t*)&l1,
                                 *(uint32_t*)&l2, *(uint32_t*)&l3);
            }
            *(uint4*)(sAhi + r * LD + ck * 8) = hi4;
            *(uint4*)(sAlo + r * LD + ck * 8) = lo4;
        } else {
            const __nv_bfloat16* Ahi = (const __nv_bfloat16*)Asrc;
            uint4 va = make_uint4(0, 0, 0, 0), vb = va;
            if (m < M) {
                va = __ldg((const uint4*)(Ahi + (size_t)m * DIM) + ck);
                vb = __ldg((const uint4*)(Alo + (size_t)m * DIM) + ck);
            }
            *(uint4*)(sAhi + r * LD + ck * 8) = va;
            *(uint4*)(sAlo + r * LD + ck * 8) = vb;
        }
    }
    // ---- stage W tiles (128 rows x 16 chunks = 2048 items; 4 iters) ----
    for (int idx = tid; idx < 2048; idx += 512) {
        int r  = idx >> 4;
        int ck = idx & 15;
        uint4 wa = __ldg((const uint4*)(Whi + (size_t)r * DIM) + ck);
        uint4 wb = __ldg((const uint4*)(Wlo + (size_t)r * DIM) + ck);
        *(uint4*)(sWhi + r * LD + ck * 8) = wa;
        *(uint4*)(sWlo + r * LD + ck * 8) = wb;
    }
    __syncthreads();

    const int mw = wid >> 2;          // 0..3 -> 16-row slabs
    const int nw = wid & 3;           // 0..3 -> 32-col slabs
    const int mBase = mw * 16;
    const int nBase = nw * 32;

    float acc[4][4];
    #pragma unroll
    for (int j = 0; j < 4; ++j)
        #pragma unroll
        for (int q = 0; q < 4; ++q) acc[j][q] = 0.f;

    // ldmatrix per-lane source addresses (byte offsets inside a tile)
    const uint32_t aRowOff = (uint32_t)(mBase + (lane & 15)) * (LD * 2) + ((lane >> 4) << 4);
    const uint32_t bRowOff = (uint32_t)(nBase + (lane & 7)) * (LD * 2) + (((lane >> 3) & 1) << 4);

    const uint32_t sb     = smem_u32(sm);
    const uint32_t offAhi = 0;
    const uint32_t offAlo = A_TILE * 2;
    const uint32_t offWhi = A_TILE * 4;
    const uint32_t offWlo = A_TILE * 4 + W_TILE * 2;

    #pragma unroll 1
    for (int pass = 0; pass < 3; ++pass) {
        const uint32_t aBase = sb + ((pass == 2) ? offAlo : offAhi) + aRowOff;
        const uint32_t bBase = sb + ((pass == 1) ? offWlo : offWhi) + bRowOff;

        #pragma unroll 1
        for (int k = 0; k < 8; ++k) {          // k16 steps, +32B each
            uint32_t a[4];
            {
                uint32_t addr = aBase + k * 32;
                asm volatile("ldmatrix.sync.aligned.m8n8.x4.shared.b16 {%0,%1,%2,%3}, [%4];"
                             : "=r"(a[0]), "=r"(a[1]), "=r"(a[2]), "=r"(a[3])
                             : "r"(addr));
            }
            uint32_t b[4][2];
            #pragma unroll
            for (int nt = 0; nt < 4; ++nt) {
                uint32_t addr = bBase + (uint32_t)(nt * 8) * (LD * 2) + k * 32;
                asm volatile("ldmatrix.sync.aligned.m8n8.x2.shared.b16 {%0,%1}, [%2];"
                             : "=r"(b[nt][0]), "=r"(b[nt][1])
                             : "r"(addr));
            }
            #pragma unroll
            for (int nt = 0; nt < 4; ++nt) {
                asm volatile(
                    "mma.sync.aligned.m16n8k16.row.col.f32.bf16.bf16.f32 "
                    "{%0,%1,%2,%3}, {%4,%5,%6,%7}, {%8,%9}, {%0,%1,%2,%3};"
                    : "+f"(acc[nt][0]), "+f"(acc[nt][1]),
                      "+f"(acc[nt][2]), "+f"(acc[nt][3])
                    : "r"(a[0]), "r"(a[1]), "r"(a[2]), "r"(a[3]),
                      "r"(b[nt][0]), "r"(b[nt][1]));
            }
        }
    }

    // ---- epilogue: + bias, fp32 store ----
    const int r0 = lane >> 2;           // 0..7
    const int c0 = (lane & 3) * 2;      // 0,2,4,6
    #pragma unroll
    for (int nt = 0; nt < 4; ++nt) {
        int coln = nBase + nt * 8 + c0;
        float2 bv = __ldg((const float2*)(bias + coln));
        int row = m0 + mBase + r0;
        if (row < M) {
            float2 v0 = make_float2(acc[nt][0] + bv.x, acc[nt][1] + bv.y);
            *(float2*)(out + (size_t)row * DIM + coln) = v0;
        }
        if (row + 8 < M) {
            float2 v1 = make_float2(acc[nt][2] + bv.x, acc[nt][3] + bv.y);
            *(float2*)(out + (size_t)(row + 8) * DIM + coln) = v1;
        }
    }
}

// ---------------------------------------------------------------------------
// kernel_launch
// ---------------------------------------------------------------------------
extern "C" void kernel_launch(void* const* d_in, const int* in_sizes, int n_in,
                              void* d_out, int out_size)
{
    const float* x   = (const float*)d_in[0];
    const void*  ei  = d_in[1];
    const float* W1  = (const float*)d_in[2];
    const float* b1  = (const float*)d_in[3];
    const float* W2  = (const float*)d_in[4];
    const float* b2  = (const float*)d_in[5];
    const float* W3  = (const float*)d_in[6];
    const float* b3  = (const float*)d_in[7];
    float*       out = (float*)d_out;

    const int N = in_sizes[0] / DIM;
    const int E = in_sizes[1] / 2;

    float* h;             cudaGetSymbolAddress((void**)&h,      g_h);
    __nv_bfloat16* ahi;   cudaGetSymbolAddress((void**)&ahi,    g_ahi);
    __nv_bfloat16* alo;   cudaGetSymbolAddress((void**)&alo,    g_alo);
    __nv_bfloat16* whi;   cudaGetSymbolAddress((void**)&whi,    g_whi);
    __nv_bfloat16* wlo;   cudaGetSymbolAddress((void**)&wlo,    g_wlo);
    float* rdeg;          cudaGetSymbolAddress((void**)&rdeg,   g_rdeg);
    int*   row;           cudaGetSymbolAddress((void**)&row,    g_row);
    int*   col;           cudaGetSymbolAddress((void**)&col,    g_col);
    int*   cnt;           cudaGetSymbolAddress((void**)&cnt,    g_cnt);
    int*   offs;          cudaGetSymbolAddress((void**)&offs,   g_offs);
    int*   cursor;        cudaGetSymbolAddress((void**)&cursor, g_cursor);
    int*   srcs;          cudaGetSymbolAddress((void**)&srcs,   g_srcs);
    int*   bsum;          cudaGetSymbolAddress((void**)&bsum,   g_bsum);
    int*   flag;          cudaGetSymbolAddress((void**)&flag,   g_is32);

    const int egrid = (E + 255) / 256;
    const int ngrid = (N + 255) / 256;
    const int nb    = (N + 1023) / 1024;
    const int wgrid = (N + 7) / 8;
    const int ggrid = (N + BM - 1) / BM;

    cudaFuncSetAttribute(tc_gemm_kernel<true>,
                         cudaFuncAttributeMaxDynamicSharedMemorySize, SMEM_GEMM_BYTES);
    cudaFuncSetAttribute(tc_gemm_kernel<false>,
                         cudaFuncAttributeMaxDynamicSharedMemorySize, SMEM_GEMM_BYTES);

    // 0) zero cnt + dtype probe + weight split (one kernel), then
    //    normalize edge indices + count in-degrees
    zero_probe_splitw_kernel<<<egrid, 256>>>(
        (const unsigned*)ei, E, cnt, N, flag,
        (const float4*)W1, (const float4*)W2, (const float4*)W3,
        (__nv_bfloat162*)whi, (__nv_bfloat162*)wlo);
    convert_count_kernel<<<egrid, 256>>>(ei, row, col, cnt, E, flag);

    // 1) CSR build
    scan1_kernel<<<nb, 1024>>>(cnt, offs, bsum, N);
    scan2_kernel<<<1, 1024>>>(bsum, nb);
    scan3_kernel<<<ngrid, 256>>>(offs, bsum, cnt, cursor, rdeg, N);
    fill_kernel<<<egrid, 256>>>(row, col, cursor, srcs, E);

    // 2) layer 1: h = x @ W1^T + b1   (fp32 x split inline during staging)
    tc_gemm_kernel<true><<<ggrid, 512, SMEM_GEMM_BYTES>>>(
        x, nullptr, whi, wlo, b1, h, N);

    // 3) mp 1: (ahi, alo) = split(relu(mean of in-neighbors of h))
    aggregate_kernel<<<wgrid, 256>>>(h, offs, cnt, srcs, rdeg,
                                     (__nv_bfloat162*)ahi, (__nv_bfloat162*)alo, N);

    // 4) layer 2
    tc_gemm_kernel<false><<<ggrid, 512, SMEM_GEMM_BYTES>>>(
        ahi, alo, whi + DIM * DIM, wlo + DIM * DIM, b2, h, N);

    // 5) mp 2
    aggregate_kernel<<<wgrid, 256>>>(h, offs, cnt, srcs, rdeg,
                                     (__nv_bfloat162*)ahi, (__nv_bfloat162*)alo, N);

    // 6) layer 3: out = agg @ W3^T + b3
    tc_gemm_kernel<false><<<ggrid, 512, SMEM_GEMM_BYTES>>>(
        ahi, alo, whi + 2 * DIM * DIM, wlo + 2 * DIM * DIM, b3, out, N);
}

// round 12
// speedup vs baseline: 1.1661x; 1.0001x over previous
#include <cuda_runtime.h>
#include <cuda_bf16.h>
#include <stdint.h>

typedef unsigned long long u64;

// Problem constants (fixed shapes for this problem)
#define MAXN 100000
#define MAXE 800000
#define DIM  128
#define LD   136   // padded SMEM row stride in bf16 (272B: 16B-aligned, ldmatrix conflict-free)

// Scratch (device globals — no allocation allowed)
__device__ float         g_h[(size_t)MAXN * DIM];      // activations (layer1 out)
__device__ float         g_h2[(size_t)MAXN * DIM];     // activations (layer2 out)
__device__ __nv_bfloat16 g_whi[3 * DIM * DIM];         // W1/W2/W3 hi
__device__ __nv_bfloat16 g_wlo[3 * DIM * DIM];         // W1/W2/W3 lo
__device__ float g_rdeg[MAXN];
__device__ int   g_row[MAXE];
__device__ int   g_col[MAXE];
__device__ int   g_cnt[MAXN];
__device__ int   g_offs[MAXN];
__device__ int   g_cursor[MAXN];
__device__ int   g_srcs[MAXE];
__device__ int   g_bsum[1024];
__device__ int   g_is32;   // monotone under atomicOr; input-fixed -> never re-zeroed

__device__ __forceinline__ uint32_t smem_u32(const void* p) {
    uint32_t a;
    asm("{ .reg .u64 t; cvta.to.shared.u64 t, %1; cvt.u32.u64 %0, t; }" : "=r"(a) : "l"(p));
    return a;
}

// ---------------------------------------------------------------------------
// fp32 -> split bf16 (hi + lo)
// ---------------------------------------------------------------------------
__device__ __forceinline__ void split2(float a, float b,
                                       __nv_bfloat162& hi, __nv_bfloat162& lo) {
    __nv_bfloat16 ha = __float2bfloat16_rn(a);
    __nv_bfloat16 hb = __float2bfloat16_rn(b);
    hi = __nv_bfloat162(ha, hb);
    lo = __floats2bfloat162_rn(a - __bfloat162float(ha), b - __bfloat162float(hb));
}

// ---------------------------------------------------------------------------
// Fused: zero cnt[] + dtype probe + weight split (all independent).
// ---------------------------------------------------------------------------
__global__ void zero_probe_splitw_kernel(
    const unsigned* __restrict__ w, int E,
    int* __restrict__ cnt, int n,
    int* __restrict__ flag,
    const float4* __restrict__ W1, const float4* __restrict__ W2,
    const float4* __restrict__ W3,
    __nv_bfloat162* __restrict__ whi, __nv_bfloat162* __restrict__ wlo)
{
    int i = blockIdx.x * blockDim.x + threadIdx.x;
    if (i < n) cnt[i] = 0;
    if (i < E) {
        if (w[2 * i + 1] != 0u) atomicOr(flag, 1);
    }
    if (i < 3 * 4096) {
        int layer = i / 4096, j = i % 4096;
        const float4* W = (layer == 0) ? W1 : (layer == 1) ? W2 : W3;
        float4 v = __ldg(W + j);
        __nv_bfloat162 h0, l0, h1, l1;
        split2(v.x, v.y, h0, l0);
        split2(v.z, v.w, h1, l1);
        whi[2 * i] = h0;  whi[2 * i + 1] = h1;
        wlo[2 * i] = l0;  wlo[2 * i + 1] = l1;
    }
}

__global__ void convert_count_kernel(const void* __restrict__ ei,
                                     int* __restrict__ row, int* __restrict__ col,
                                     int* __restrict__ cnt,
                                     int E, const int* __restrict__ flag) {
    int i = blockIdx.x * blockDim.x + threadIdx.x;
    if (i >= E) return;
    int r, c;
    if (*flag) {
        const int* p = (const int*)ei;
        r = p[i];
        c = p[E + i];
    } else {
        const long long* p = (const long long*)ei;
        r = (int)p[i];
        c = (int)p[E + i];
    }
    row[i] = r;
    col[i] = c;
    atomicAdd(&cnt[r], 1);
}

__global__ void scan1_kernel(const int* __restrict__ cnt, int* __restrict__ offs,
                             int* __restrict__ bsum, int n) {
    __shared__ int sh[1024];
    int i = blockIdx.x * 1024 + threadIdx.x;
    int v = (i < n) ? cnt[i] : 0;
    sh[threadIdx.x] = v;
    __syncthreads();
    #pragma unroll
    for (int d = 1; d < 1024; d <<= 1) {
        int t = (threadIdx.x >= d) ? sh[threadIdx.x - d] : 0;
        __syncthreads();
        sh[threadIdx.x] += t;
        __syncthreads();
    }
    if (i < n) offs[i] = sh[threadIdx.x] - v;
    if (threadIdx.x == 1023) bsum[blockIdx.x] = sh[1023];
}

__global__ void scan2_kernel(int* __restrict__ bsum, int nb) {
    __shared__ int sh[1024];
    int v = (threadIdx.x < nb) ? bsum[threadIdx.x] : 0;
    sh[threadIdx.x] = v;
    __syncthreads();
    #pragma unroll
    for (int d = 1; d < 1024; d <<= 1) {
        int t = (threadIdx.x >= d) ? sh[threadIdx.x - d] : 0;
        __syncthreads();
        sh[threadIdx.x] += t;
        __syncthreads();
    }
    if (threadIdx.x < nb) bsum[threadIdx.x] = sh[threadIdx.x] - v;
}

__global__ void scan3_kernel(int* __restrict__ offs, const int* __restrict__ bsum,
                             const int* __restrict__ cnt, int* __restrict__ cursor,
                             float* __restrict__ rdeg, int n) {
    int i = blockIdx.x * blockDim.x + threadIdx.x;
    if (i >= n) return;
    int o = offs[i] + bsum[i >> 10];
    offs[i] = o;
    cursor[i] = o;
    rdeg[i] = 1.0f / fmaxf((float)cnt[i], 1.0f);
}

__global__ void fill_kernel(const int* __restrict__ row, const int* __restrict__ col,
                            int* __restrict__ cursor, int* __restrict__ srcs, int E) {
    int e = blockIdx.x * blockDim.x + threadIdx.x;
    if (e >= E) return;
    int idx = atomicAdd(&cursor[row[e]], 1);
    srcs[idx] = col[e];
}

// ---------------------------------------------------------------------------
// Tensor-core split-bf16 GEMM via mma.sync (HMMA pipe):
//   out[M,128] = A[M,128] @ W[128,128]^T + bias
//   D = Ahi@Whi + Ahi@Wlo + Alo@Whi  (3 sequential passes, fp32 acc)
// CTA: 64x128, 104KB SMEM -> 2 CTAs/SM so one CTA's A-staging (gather)
// overlaps the other's MMA. 16 warps (512 threads) 4x4; warp = 16x32.
//
// A-staging modes:
//   AGG=false: A = fp32 matrix (layer 1's x); split hi/lo inline.
//   AGG=true : A = relu(mean of in-neighbors of Asrc) computed IN-CTA from
//              CSR (fused message passing). Output must NOT alias Asrc.
// ---------------------------------------------------------------------------
#define BM 64
#define A_TILE (BM * LD)                     // bf16 elements per A tile
#define W_TILE (128 * LD)                    // bf16 elements per W tile
#define SMEM_GEMM_BYTES ((2 * A_TILE + 2 * W_TILE) * 2)   // 104,448 B

template <bool AGG>
__global__ __launch_bounds__(512, 2) void tc_gemm_kernel(
    const float* __restrict__ Asrc,          // AGG ? hsrc : x
    const int* __restrict__ offs,
    const int* __restrict__ cnt,
    const int* __restrict__ srcs,
    const float* __restrict__ rdeg,
    const __nv_bfloat16* __restrict__ Whi,
    const __nv_bfloat16* __restrict__ Wlo,
    const float* __restrict__ bias,
    float* __restrict__ out,
    int M)
{
    extern __shared__ __nv_bfloat16 sm[];
    const int tid  = threadIdx.x;
    const int wid  = tid >> 5;
    const int lane = tid & 31;
    const int m0   = blockIdx.x * BM;

    __nv_bfloat16* sAhi = sm;
    __nv_bfloat16* sAlo = sAhi + A_TILE;
    __nv_bfloat16* sWhi = sAlo + A_TILE;
    __nv_bfloat16* sWlo = sWhi + W_TILE;

    // ---- stage W tiles (128 rows x 16 chunks = 2048 items; 4 iters) ----
    for (int idx = tid; idx < 2048; idx += 512) {
        int r  = idx >> 4;
        int ck = idx & 15;
        uint4 wa = __ldg((const uint4*)(Whi + (size_t)r * DIM) + ck);
        uint4 wb = __ldg((const uint4*)(Wlo + (size_t)r * DIM) + ck);
        *(uint4*)(sWhi + r * LD + ck * 8) = wa;
        *(uint4*)(sWlo + r * LD + ck * 8) = wb;
    }

    // ---- stage A tiles ----
    if (AGG) {
        // Fused message passing: warp w handles rows w*4 .. w*4+3.
        // Lane owns a 16B chunk (4 floats) of the 512B row.
        #pragma unroll 1
        for (int i = 0; i < 4; ++i) {
            int r = wid * 4 + i;
            int node = m0 + r;
            float4 acc = make_float4(0.f, 0.f, 0.f, 0.f);
            if (node < M) {
                int start = __ldg(offs + node);
                int c     = __ldg(cnt + node);
                int j = 0;
                for (; j + 4 <= c; j += 4) {
                    int s0 = __ldg(srcs + start + j);
                    int s1 = __ldg(srcs + start + j + 1);
                    int s2 = __ldg(srcs + start + j + 2);
                    int s3 = __ldg(srcs + start + j + 3);
                    float4 v0 = __ldg((const float4*)(Asrc + (size_t)s0 * DIM) + lane);
                    float4 v1 = __ldg((const float4*)(Asrc + (size_t)s1 * DIM) + lane);
                    float4 v2 = __ldg((const float4*)(Asrc + (size_t)s2 * DIM) + lane);
                    float4 v3 = __ldg((const float4*)(Asrc + (size_t)s3 * DIM) + lane);
                    acc.x += (v0.x + v1.x) + (v2.x + v3.x);
                    acc.y += (v0.y + v1.y) + (v2.y + v3.y);
                    acc.z += (v0.z + v1.z) + (v2.z + v3.z);
                    acc.w += (v0.w + v1.w) + (v2.w + v3.w);
                }
                for (; j < c; ++j) {
                    int s0 = __ldg(srcs + start + j);
                    float4 v0 = __ldg((const float4*)(Asrc + (size_t)s0 * DIM) + lane);
                    acc.x += v0.x;
                    acc.y += v0.y;
                    acc.z += v0.z;
                    acc.w += v0.w;
                }
                float rd = __ldg(rdeg + node);
                acc.x = fmaxf(acc.x * rd, 0.f);
                acc.y = fmaxf(acc.y * rd, 0.f);
                acc.z = fmaxf(acc.z * rd, 0.f);
                acc.w = fmaxf(acc.w * rd, 0.f);
            }
            __nv_bfloat162 h0, l0, h1, l1;
            split2(acc.x, acc.y, h0, l0);
            split2(acc.z, acc.w, h1, l1);
            *(uint2*)(sAhi + r * LD + lane * 4) =
                make_uint2(*(uint32_t*)&h0, *(uint32_t*)&h1);
            *(uint2*)(sAlo + r * LD + lane * 4) =
                make_uint2(*(uint32_t*)&l0, *(uint32_t*)&l1);
        }
    } else {
        // Layer 1: read fp32 x, split inline.
        for (int idx = tid; idx < BM * 16; idx += 512) {
            int r  = idx >> 4;
            int ck = idx & 15;
            int m  = m0 + r;
            uint4 hi4 = make_uint4(0, 0, 0, 0), lo4 = hi4;
            if (m < M) {
                float4 va = __ldg((const float4*)(Asrc + (size_t)m * DIM + ck * 8));
                float4 vb = __ldg((const float4*)(Asrc + (size_t)m * DIM + ck * 8) + 1);
                __nv_bfloat162 h0, l0, h1, l1, h2, l2, h3, l3;
                split2(va.x, va.y, h0, l0);
                split2(va.z, va.w, h1, l1);
                split2(vb.x, vb.y, h2, l2);
                split2(vb.z, vb.w, h3, l3);
                hi4 = make_uint4(*(uint32_t*)&h0, *(uint32_t*)&h1,
                                 *(uint32_t*)&h2, *(uint32_t*)&h3);
                lo4 = make_uint4(*(uint32_t*)&l0, *(uint32_t*)&l1,
                                 *(uint32_t*)&l2, *(uint32_t*)&l3);
            }
            *(uint4*)(sAhi + r * LD + ck * 8) = hi4;
            *(uint4*)(sAlo + r * LD + ck * 8) = lo4;
        }
    }
    __syncthreads();

    const int mw = wid >> 2;          // 0..3 -> 16-row slabs
    const int nw = wid & 3;           // 0..3 -> 32-col slabs
    const int mBase = mw * 16;
    const int nBase = nw * 32;

    float acc[4][4];
    #pragma unroll
    for (int j = 0; j < 4; ++j)
        #pragma unroll
        for (int q = 0; q < 4; ++q) acc[j][q] = 0.f;

    // ldmatrix per-lane source addresses (byte offsets inside a tile)
    const uint32_t aRowOff = (uint32_t)(mBase + (lane & 15)) * (LD * 2) + ((lane >> 4) << 4);
    const uint32_t bRowOff = (uint32_t)(nBase + (lane & 7)) * (LD * 2) + (((lane >> 3) & 1) << 4);

    const uint32_t sb     = smem_u32(sm);
    const uint32_t offAhi = 0;
    const uint32_t offAlo = A_TILE * 2;
    const uint32_t offWhi = A_TILE * 4;
    const uint32_t offWlo = A_TILE * 4 + W_TILE * 2;

    #pragma unroll 1
    for (int pass = 0; pass < 3; ++pass) {
        const uint32_t aBase = sb + ((pass == 2) ? offAlo : offAhi) + aRowOff;
        const uint32_t bBase = sb + ((pass == 1) ? offWlo : offWhi) + bRowOff;

        #pragma unroll 1
        for (int k = 0; k < 8; ++k) {          // k16 steps, +32B each
            uint32_t a[4];
            {
                uint32_t addr = aBase + k * 32;
                asm volatile("ldmatrix.sync.aligned.m8n8.x4.shared.b16 {%0,%1,%2,%3}, [%4];"
                             : "=r"(a[0]), "=r"(a[1]), "=r"(a[2]), "=r"(a[3])
                             : "r"(addr));
            }
            uint32_t b[4][2];
            #pragma unroll
            for (int nt = 0; nt < 4; ++nt) {
                uint32_t addr = bBase + (uint32_t)(nt * 8) * (LD * 2) + k * 32;
                asm volatile("ldmatrix.sync.aligned.m8n8.x2.shared.b16 {%0,%1}, [%2];"
                             : "=r"(b[nt][0]), "=r"(b[nt][1])
                             : "r"(addr));
            }
            #pragma unroll
            for (int nt = 0; nt < 4; ++nt) {
                asm volatile(
                    "mma.sync.aligned.m16n8k16.row.col.f32.bf16.bf16.f32 "
                    "{%0,%1,%2,%3}, {%4,%5,%6,%7}, {%8,%9}, {%0,%1,%2,%3};"
                    : "+f"(acc[nt][0]), "+f"(acc[nt][1]),
                      "+f"(acc[nt][2]), "+f"(acc[nt][3])
                    : "r"(a[0]), "r"(a[1]), "r"(a[2]), "r"(a[3]),
                      "r"(b[nt][0]), "r"(b[nt][1]));
            }
        }
    }

    // ---- epilogue: + bias, fp32 store ----
    const int r0 = lane >> 2;           // 0..7
    const int c0 = (lane & 3) * 2;      // 0,2,4,6
    #pragma unroll
    for (int nt = 0; nt < 4; ++nt) {
        int coln = nBase + nt * 8 + c0;
        float2 bv = __ldg((const float2*)(bias + coln));
        int row = m0 + mBase + r0;
        if (row < M) {
            float2 v0 = make_float2(acc[nt][0] + bv.x, acc[nt][1] + bv.y);
            *(float2*)(out + (size_t)row * DIM + coln) = v0;
        }
        if (row + 8 < M) {
            float2 v1 = make_float2(acc[nt][2] + bv.x, acc[nt][3] + bv.y);
            *(float2*)(out + (size_t)(row + 8) * DIM + coln) = v1;
        }
    }
}

// ---------------------------------------------------------------------------
// kernel_launch
// ---------------------------------------------------------------------------
extern "C" void kernel_launch(void* const* d_in, const int* in_sizes, int n_in,
                              void* d_out, int out_size)
{
    const float* x   = (const float*)d_in[0];
    const void*  ei  = d_in[1];
    const float* W1  = (const float*)d_in[2];
    const float* b1  = (const float*)d_in[3];
    const float* W2  = (const float*)d_in[4];
    const float* b2  = (const float*)d_in[5];
    const float* W3  = (const float*)d_in[6];
    const float* b3  = (const float*)d_in[7];
    float*       out = (float*)d_out;

    const int N = in_sizes[0] / DIM;
    const int E = in_sizes[1] / 2;

    float* h;             cudaGetSymbolAddress((void**)&h,      g_h);
    float* h2;            cudaGetSymbolAddress((void**)&h2,     g_h2);
    __nv_bfloat16* whi;   cudaGetSymbolAddress((void**)&whi,    g_whi);
    __nv_bfloat16* wlo;   cudaGetSymbolAddress((void**)&wlo,    g_wlo);
    float* rdeg;          cudaGetSymbolAddress((void**)&rdeg,   g_rdeg);
    int*   row;           cudaGetSymbolAddress((void**)&row,    g_row);
    int*   col;           cudaGetSymbolAddress((void**)&col,    g_col);
    int*   cnt;           cudaGetSymbolAddress((void**)&cnt,    g_cnt);
    int*   offs;          cudaGetSymbolAddress((void**)&offs,   g_offs);
    int*   cursor;        cudaGetSymbolAddress((void**)&cursor, g_cursor);
    int*   srcs;          cudaGetSymbolAddress((void**)&srcs,   g_srcs);
    int*   bsum;          cudaGetSymbolAddress((void**)&bsum,   g_bsum);
    int*   flag;          cudaGetSymbolAddress((void**)&flag,   g_is32);

    const int egrid = (E + 255) / 256;
    const int ngrid = (N + 255) / 256;
    const int nb    = (N + 1023) / 1024;
    const int ggrid = (N + BM - 1) / BM;

    cudaFuncSetAttribute(tc_gemm_kernel<true>,
                         cudaFuncAttributeMaxDynamicSharedMemorySize, SMEM_GEMM_BYTES);
    cudaFuncSetAttribute(tc_gemm_kernel<false>,
                         cudaFuncAttributeMaxDynamicSharedMemorySize, SMEM_GEMM_BYTES);

    // 0) zero cnt + dtype probe + weight split, then normalize + count
    zero_probe_splitw_kernel<<<egrid, 256>>>(
        (const unsigned*)ei, E, cnt, N, flag,
        (const float4*)W1, (const float4*)W2, (const float4*)W3,
        (__nv_bfloat162*)whi, (__nv_bfloat162*)wlo);
    convert_count_kernel<<<egrid, 256>>>(ei, row, col, cnt, E, flag);

    // 1) CSR build
    scan1_kernel<<<nb, 1024>>>(cnt, offs, bsum, N);
    scan2_kernel<<<1, 1024>>>(bsum, nb);
    scan3_kernel<<<ngrid, 256>>>(offs, bsum, cnt, cursor, rdeg, N);
    fill_kernel<<<egrid, 256>>>(row, col, cursor, srcs, E);

    // 2) layer 1: h = x @ W1^T + b1   (fp32 x split inline during staging)
    tc_gemm_kernel<false><<<ggrid, 512, SMEM_GEMM_BYTES>>>(
        x, nullptr, nullptr, nullptr, nullptr, whi, wlo, b1, h, N);

    // 3) layer 2 (fused mp): h2 = relu(mean_nbrs(h)) @ W2^T + b2
    tc_gemm_kernel<true><<<ggrid, 512, SMEM_GEMM_BYTES>>>(
        h, offs, cnt, srcs, rdeg, whi + DIM * DIM, wlo + DIM * DIM, b2, h2, N);

    // 4) layer 3 (fused mp): out = relu(mean_nbrs(h2)) @ W3^T + b3
    tc_gemm_kernel<true><<<ggrid, 512, SMEM_GEMM_BYTES>>>(
        h2, offs, cnt, srcs, rdeg, whi + 2 * DIM * DIM, wlo + 2 * DIM * DIM, b3, out, N);
}

// round 13
// speedup vs baseline: 1.1914x; 1.0218x over previous
#include <cuda_runtime.h>
#include <cuda_bf16.h>
#include <stdint.h>

typedef unsigned long long u64;

// Problem constants (fixed shapes for this problem)
#define MAXN 100000
#define MAXE 800000
#define DIM  128
#define LD   136   // padded SMEM row stride in bf16 (272B: 16B-aligned, ldmatrix conflict-free)

// Scratch (device globals — no allocation allowed)
__device__ float         g_h[(size_t)MAXN * DIM];      // fp32 activations (GEMM out)
__device__ __nv_bfloat16 g_ahi[(size_t)MAXN * DIM];    // split-bf16 GEMM input (hi)
__device__ __nv_bfloat16 g_alo[(size_t)MAXN * DIM];    // split-bf16 GEMM input (lo)
__device__ __nv_bfloat16 g_whi[3 * DIM * DIM];         // W1/W2/W3 hi
__device__ __nv_bfloat16 g_wlo[3 * DIM * DIM];         // W1/W2/W3 lo
__device__ float g_rdeg[MAXN];
__device__ int   g_row[MAXE];
__device__ int   g_col[MAXE];
__device__ int   g_cnt[MAXN];
__device__ int   g_offs[MAXN];
__device__ int   g_cursor[MAXN];
__device__ int   g_srcs[MAXE];
__device__ int   g_bsum[1024];
__device__ int   g_is32;   // monotone under atomicOr; input-fixed -> never re-zeroed

__device__ __forceinline__ uint32_t smem_u32(const void* p) {
    uint32_t a;
    asm("{ .reg .u64 t; cvta.to.shared.u64 t, %1; cvt.u32.u64 %0, t; }" : "=r"(a) : "l"(p));
    return a;
}

// ---------------------------------------------------------------------------
// fp32 -> split bf16 (hi + lo)
// ---------------------------------------------------------------------------
__device__ __forceinline__ void split2(float a, float b,
                                       __nv_bfloat162& hi, __nv_bfloat162& lo) {
    __nv_bfloat16 ha = __float2bfloat16_rn(a);
    __nv_bfloat16 hb = __float2bfloat16_rn(b);
    hi = __nv_bfloat162(ha, hb);
    lo = __floats2bfloat162_rn(a - __bfloat162float(ha), b - __bfloat162float(hb));
}

// ---------------------------------------------------------------------------
// Fused: zero cnt[] + dtype probe + weight split (all independent).
// Probe: int64 values < 2^31 have zero high words; int32 probed words are
// random indices (mostly nonzero).
// ---------------------------------------------------------------------------
__global__ void zero_probe_splitw_kernel(
    const unsigned* __restrict__ w, int E,
    int* __restrict__ cnt, int n,
    int* __restrict__ flag,
    const float4* __restrict__ W1, const float4* __restrict__ W2,
    const float4* __restrict__ W3,
    __nv_bfloat162* __restrict__ whi, __nv_bfloat162* __restrict__ wlo)
{
    int i = blockIdx.x * blockDim.x + threadIdx.x;
    if (i < n) cnt[i] = 0;
    if (i < E) {
        if (w[2 * i + 1] != 0u) atomicOr(flag, 1);
    }
    if (i < 3 * 4096) {
        int layer = i / 4096, j = i % 4096;
        const float4* W = (layer == 0) ? W1 : (layer == 1) ? W2 : W3;
        float4 v = __ldg(W + j);
        __nv_bfloat162 h0, l0, h1, l1;
        split2(v.x, v.y, h0, l0);
        split2(v.z, v.w, h1, l1);
        whi[2 * i] = h0;  whi[2 * i + 1] = h1;
        wlo[2 * i] = l0;  wlo[2 * i + 1] = l1;
    }
}

__global__ void convert_count_kernel(const void* __restrict__ ei,
                                     int* __restrict__ row, int* __restrict__ col,
                                     int* __restrict__ cnt,
                                     int E, const int* __restrict__ flag) {
    int i = blockIdx.x * blockDim.x + threadIdx.x;
    if (i >= E) return;
    int r, c;
    if (*flag) {
        const int* p = (const int*)ei;
        r = p[i];
        c = p[E + i];
    } else {
        const long long* p = (const long long*)ei;
        r = (int)p[i];
        c = (int)p[E + i];
    }
    row[i] = r;
    col[i] = c;
    atomicAdd(&cnt[r], 1);
}

__global__ void scan1_kernel(const int* __restrict__ cnt, int* __restrict__ offs,
                             int* __restrict__ bsum, int n) {
    __shared__ int sh[1024];
    int i = blockIdx.x * 1024 + threadIdx.x;
    int v = (i < n) ? cnt[i] : 0;
    sh[threadIdx.x] = v;
    __syncthreads();
    #pragma unroll
    for (int d = 1; d < 1024; d <<= 1) {
        int t = (threadIdx.x >= d) ? sh[threadIdx.x - d] : 0;
        __syncthreads();
        sh[threadIdx.x] += t;
        __syncthreads();
    }
    if (i < n) offs[i] = sh[threadIdx.x] - v;   // exclusive within block
    if (threadIdx.x == 1023) bsum[blockIdx.x] = sh[1023];
}

// scan3: finalize offsets. Each block re-derives the (<=256-entry) exclusive
// prefix of bsum in SMEM (8-step Hillis-Steele) — removes the grid=1 scan2
// launch and its latency bubble.
__global__ void scan3_kernel(int* __restrict__ offs, const int* __restrict__ bsum,
                             int nb,
                             const int* __restrict__ cnt, int* __restrict__ cursor,
                             float* __restrict__ rdeg, int n) {
    __shared__ int sh[256];
    int t = threadIdx.x;
    int v = (t < nb) ? bsum[t] : 0;
    sh[t] = v;
    __syncthreads();
    #pragma unroll
    for (int d = 1; d < 256; d <<= 1) {
        int tv = (t >= d) ? sh[t - d] : 0;
        __syncthreads();
        sh[t] += tv;
        __syncthreads();
    }
    int i = blockIdx.x * 256 + t;
    if (i >= n) return;
    int blk = i >> 10;
    int base = (blk == 0) ? 0 : sh[blk - 1];   // exclusive prefix of block sums
    int o = offs[i] + base;
    offs[i] = o;
    cursor[i] = o;
    rdeg[i] = 1.0f / fmaxf((float)cnt[i], 1.0f);
}

__global__ void fill_kernel(const int* __restrict__ row, const int* __restrict__ col,
                            int* __restrict__ cursor, int* __restrict__ srcs, int E) {
    int e = blockIdx.x * blockDim.x + threadIdx.x;
    if (e >= E) return;
    int idx = atomicAdd(&cursor[row[e]], 1);
    srcs[idx] = col[e];
}

// ---------------------------------------------------------------------------
// Pull-mode aggregate: relu(mean of in-neighbors) -> split bf16 (hi, lo)
// One warp per node; lane owns 4 floats. Unrolled x4 for MLP.
// ---------------------------------------------------------------------------
__global__ __launch_bounds__(256) void aggregate_kernel(
    const float* __restrict__ h,
    const int* __restrict__ offs,
    const int* __restrict__ cnt,
    const int* __restrict__ srcs,
    const float* __restrict__ rdeg,
    __nv_bfloat162* __restrict__ ahi,
    __nv_bfloat162* __restrict__ alo,
    int N)
{
    int node = blockIdx.x * 8 + (threadIdx.x >> 5);
    if (node >= N) return;
    int lane = threadIdx.x & 31;

    int start = __ldg(offs + node);
    int c     = __ldg(cnt + node);

    float4 acc = make_float4(0.f, 0.f, 0.f, 0.f);
    int j = 0;
    for (; j + 4 <= c; j += 4) {
        int s0 = __ldg(srcs + start + j);
        int s1 = __ldg(srcs + start + j + 1);
        int s2 = __ldg(srcs + start + j + 2);
        int s3 = __ldg(srcs + start + j + 3);
        float4 v0 = __ldg((const float4*)(h + (size_t)s0 * DIM) + lane);
        float4 v1 = __ldg((const float4*)(h + (size_t)s1 * DIM) + lane);
        float4 v2 = __ldg((const float4*)(h + (size_t)s2 * DIM) + lane);
        float4 v3 = __ldg((const float4*)(h + (size_t)s3 * DIM) + lane);
        acc.x += (v0.x + v1.x) + (v2.x + v3.x);
        acc.y += (v0.y + v1.y) + (v2.y + v3.y);
        acc.z += (v0.z + v1.z) + (v2.z + v3.z);
        acc.w += (v0.w + v1.w) + (v2.w + v3.w);
    }
    for (; j < c; ++j) {
        int s0 = __ldg(srcs + start + j);
        float4 v0 = __ldg((const float4*)(h + (size_t)s0 * DIM) + lane);
        acc.x += v0.x;
        acc.y += v0.y;
        acc.z += v0.z;
        acc.w += v0.w;
    }

    float rd = __ldg(rdeg + node);
    float4 o;
    o.x = fmaxf(acc.x * rd, 0.f);
    o.y = fmaxf(acc.y * rd, 0.f);
    o.z = fmaxf(acc.z * rd, 0.f);
    o.w = fmaxf(acc.w * rd, 0.f);

    __nv_bfloat162 h0, l0, h1, l1;
    split2(o.x, o.y, h0, l0);
    split2(o.z, o.w, h1, l1);
    size_t base = (size_t)node * (DIM / 2) + lane * 2;
    ahi[base] = h0;  ahi[base + 1] = h1;
    alo[base] = l0;  alo[base + 1] = l1;
}

// ---------------------------------------------------------------------------
// Tensor-core split-bf16 GEMM via mma.sync (HMMA pipe):
//   out[M,128] = A[M,128] @ W[128,128]^T + bias
//   D = Ahi@Whi + Ahi@Wlo + Alo@Whi  (3 sequential passes, fp32 acc)
// CTA: 128x128, 16 warps (512 threads) in 4x4 grid; warp = 32x32 via
// 2x4 m16n8k16 tiles. (R9 config — best measured GEMM core.)
// CONVERT=true: A source is fp32 (layer 1's x); split hi/lo during staging.
// ---------------------------------------------------------------------------
#define SMEM_TILE (128 * LD)                 // bf16 elements per tile
#define SMEM_GEMM_BYTES (4 * SMEM_TILE * 2)  // 139,264 B

template <bool CONVERT>
__global__ __launch_bounds__(512, 1) void tc_gemm_kernel(
    const void* __restrict__ Asrc,           // CONVERT ? fp32[M,128] : bf16 hi
    const __nv_bfloat16* __restrict__ Alo,   // used when !CONVERT
    const __nv_bfloat16* __restrict__ Whi,
    const __nv_bfloat16* __restrict__ Wlo,
    const float* __restrict__ bias,
    float* __restrict__ out,
    int M)
{
    extern __shared__ __nv_bfloat16 sm[];
    const int tid  = threadIdx.x;
    const int wid  = tid >> 5;
    const int lane = tid & 31;
    const int m0   = blockIdx.x * 128;

    __nv_bfloat16* sAhi = sm;
    __nv_bfloat16* sAlo = sAhi + SMEM_TILE;
    __nv_bfloat16* sWhi = sAlo + SMEM_TILE;
    __nv_bfloat16* sWlo = sWhi + SMEM_TILE;

    // ---- load 4 tiles into padded SMEM (16B chunks; 4 iters/thread) ----
    for (int idx = tid; idx < 2048; idx += 512) {
        int r  = idx >> 4;      // row 0..127
        int ck = idx & 15;      // chunk of 8 bf16 (16B) / 8 fp32 (32B)
        int m  = m0 + r;
        if (CONVERT) {
            const float* x = (const float*)Asrc;
            uint4 hi4 = make_uint4(0, 0, 0, 0), lo4 = hi4;
            if (m < M) {
                float4 va = __ldg((const float4*)(x + (size_t)m * DIM + ck * 8));
                float4 vb = __ldg((const float4*)(x + (size_t)m * DIM + ck * 8) + 1);
                __nv_bfloat162 h0, l0, h1, l1, h2, l2, h3, l3;
                split2(va.x, va.y, h0, l0);
                split2(va.z, va.w, h1, l1);
                split2(vb.x, vb.y, h2, l2);
                split2(vb.z, vb.w, h3, l3);
                hi4 = make_uint4(*(uint32_t*)&h0, *(uint32_t*)&h1,
                                 *(uint32_t*)&h2, *(uint32_t*)&h3);
                lo4 = make_uint4(*(uint32_t*)&l0, *(uint32_t*)&l1,
                                 *(uint32_t*)&l2, *(uint32_t*)&l3);
            }
            *(uint4*)(sAhi + r * LD + ck * 8) = hi4;
            *(uint4*)(sAlo + r * LD + ck * 8) = lo4;
        } else {
            const __nv_bfloat16* Ahi = (const __nv_bfloat16*)Asrc;
            uint4 va = make_uint4(0, 0, 0, 0), vb = va;
            if (m < M) {
                va = __ldg((const uint4*)(Ahi + (size_t)m * DIM) + ck);
                vb = __ldg((const uint4*)(Alo + (size_t)m * DIM) + ck);
            }
            *(uint4*)(sAhi + r * LD + ck * 8) = va;
            *(uint4*)(sAlo + r * LD + ck * 8) = vb;
        }
        uint4 wa = __ldg((const uint4*)(Whi + (size_t)r * DIM) + ck);
        uint4 wb = __ldg((const uint4*)(Wlo + (size_t)r * DIM) + ck);
        *(uint4*)(sWhi + r * LD + ck * 8) = wa;
        *(uint4*)(sWlo + r * LD + ck * 8) = wb;
    }
    __syncthreads();

    const int mw = wid >> 2;          // 0..3
    const int nw = wid & 3;           // 0..3
    const int mBase = mw * 32;
    const int nBase = nw * 32;

    float acc[2][4][4];
    #pragma unroll
    for (int i = 0; i < 2; ++i)
        #pragma unroll
        for (int j = 0; j < 4; ++j)
            #pragma unroll
            for (int q = 0; q < 4; ++q) acc[i][j][q] = 0.f;

    // ldmatrix per-lane source addresses (byte offsets inside a tile)
    const uint32_t aRowOff = (uint32_t)(mBase + (lane & 15)) * (LD * 2) + ((lane >> 4) << 4);
    const uint32_t bRowOff = (uint32_t)(nBase + (lane & 7)) * (LD * 2) + (((lane >> 3) & 1) << 4);

    const uint32_t sb     = smem_u32(sm);
    const uint32_t offAhi = 0;
    const uint32_t offAlo = SMEM_TILE * 2;
    const uint32_t offWhi = SMEM_TILE * 4;
    const uint32_t offWlo = SMEM_TILE * 6;

    #pragma unroll 1
    for (int pass = 0; pass < 3; ++pass) {
        const uint32_t aBase = sb + ((pass == 2) ? offAlo : offAhi) + aRowOff;
        const uint32_t bBase = sb + ((pass == 1) ? offWlo : offWhi) + bRowOff;

        #pragma unroll 1
        for (int k = 0; k < 8; ++k) {          // k16 steps, +32B each
            uint32_t a[2][4];
            #pragma unroll
            for (int mt = 0; mt < 2; ++mt) {
                uint32_t addr = aBase + (uint32_t)(mt * 16) * (LD * 2) + k * 32;
                asm volatile("ldmatrix.sync.aligned.m8n8.x4.shared.b16 {%0,%1,%2,%3}, [%4];"
                             : "=r"(a[mt][0]), "=r"(a[mt][1]), "=r"(a[mt][2]), "=r"(a[mt][3])
                             : "r"(addr));
            }
            uint32_t b[4][2];
            #pragma unroll
            for (int nt = 0; nt < 4; ++nt) {
                uint32_t addr = bBase + (uint32_t)(nt * 8) * (LD * 2) + k * 32;
                asm volatile("ldmatrix.sync.aligned.m8n8.x2.shared.b16 {%0,%1}, [%2];"
                             : "=r"(b[nt][0]), "=r"(b[nt][1])
                             : "r"(addr));
            }
            #pragma unroll
            for (int mt = 0; mt < 2; ++mt)
                #pragma unroll
                for (int nt = 0; nt < 4; ++nt) {
                    asm volatile(
                        "mma.sync.aligned.m16n8k16.row.col.f32.bf16.bf16.f32 "
                        "{%0,%1,%2,%3}, {%4,%5,%6,%7}, {%8,%9}, {%0,%1,%2,%3};"
                        : "+f"(acc[mt][nt][0]), "+f"(acc[mt][nt][1]),
                          "+f"(acc[mt][nt][2]), "+f"(acc[mt][nt][3])
                        : "r"(a[mt][0]), "r"(a[mt][1]), "r"(a[mt][2]), "r"(a[mt][3]),
                          "r"(b[nt][0]), "r"(b[nt][1]));
                }
        }
    }

    // ---- epilogue: + bias, fp32 store ----
    const int r0 = lane >> 2;           // 0..7
    const int c0 = (lane & 3) * 2;      // 0,2,4,6
    #pragma unroll
    for (int nt = 0; nt < 4; ++nt) {
        int coln = nBase + nt * 8 + c0;
        float2 bv = __ldg((const float2*)(bias + coln));
        #pragma unroll
        for (int mt = 0; mt < 2; ++mt) {
            int row = m0 + mBase + mt * 16 + r0;
            if (row < M) {
                float2 v0 = make_float2(acc[mt][nt][0] + bv.x, acc[mt][nt][1] + bv.y);
                *(float2*)(out + (size_t)row * DIM + coln) = v0;
            }
            if (row + 8 < M) {
                float2 v1 = make_float2(acc[mt][nt][2] + bv.x, acc[mt][nt][3] + bv.y);
                *(float2*)(out + (size_t)(row + 8) * DIM + coln) = v1;
            }
        }
    }
}

// ---------------------------------------------------------------------------
// kernel_launch
// ---------------------------------------------------------------------------
extern "C" void kernel_launch(void* const* d_in, const int* in_sizes, int n_in,
                              void* d_out, int out_size)
{
    const float* x   = (const float*)d_in[0];
    const void*  ei  = d_in[1];
    const float* W1  = (const float*)d_in[2];
    const float* b1  = (const float*)d_in[3];
    const float* W2  = (const float*)d_in[4];
    const float* b2  = (const float*)d_in[5];
    const float* W3  = (const float*)d_in[6];
    const float* b3  = (const float*)d_in[7];
    float*       out = (float*)d_out;

    const int N = in_sizes[0] / DIM;
    const int E = in_sizes[1] / 2;

    float* h;             cudaGetSymbolAddress((void**)&h,      g_h);
    __nv_bfloat16* ahi;   cudaGetSymbolAddress((void**)&ahi,    g_ahi);
    __nv_bfloat16* alo;   cudaGetSymbolAddress((void**)&alo,    g_alo);
    __nv_bfloat16* whi;   cudaGetSymbolAddress((void**)&whi,    g_whi);
    __nv_bfloat16* wlo;   cudaGetSymbolAddress((void**)&wlo,    g_wlo);
    float* rdeg;          cudaGetSymbolAddress((void**)&rdeg,   g_rdeg);
    int*   row;           cudaGetSymbolAddress((void**)&row,    g_row);
    int*   col;           cudaGetSymbolAddress((void**)&col,    g_col);
    int*   cnt;           cudaGetSymbolAddress((void**)&cnt,    g_cnt);
    int*   offs;          cudaGetSymbolAddress((void**)&offs,   g_offs);
    int*   cursor;        cudaGetSymbolAddress((void**)&cursor, g_cursor);
    int*   srcs;          cudaGetSymbolAddress((void**)&srcs,   g_srcs);
    int*   bsum;          cudaGetSymbolAddress((void**)&bsum,   g_bsum);
    int*   flag;          cudaGetSymbolAddress((void**)&flag,   g_is32);

    const int egrid = (E + 255) / 256;
    const int n256  = (N + 255) / 256;
    const int nb    = (N + 1023) / 1024;   // scan blocks (<=256 required)
    const int wgrid = (N + 7) / 8;
    const int ggrid = (N + 127) / 128;

    cudaFuncSetAttribute(tc_gemm_kernel<true>,
                         cudaFuncAttributeMaxDynamicSharedMemorySize, SMEM_GEMM_BYTES);
    cudaFuncSetAttribute(tc_gemm_kernel<false>,
                         cudaFuncAttributeMaxDynamicSharedMemorySize, SMEM_GEMM_BYTES);

    // 0) zero cnt + dtype probe + weight split (one kernel), then
    //    normalize edge indices + count in-degrees
    zero_probe_splitw_kernel<<<egrid, 256>>>(
        (const unsigned*)ei, E, cnt, N, flag,
        (const float4*)W1, (const float4*)W2, (const float4*)W3,
        (__nv_bfloat162*)whi, (__nv_bfloat162*)wlo);
    convert_count_kernel<<<egrid, 256>>>(ei, row, col, cnt, E, flag);

    // 1) CSR build (scan2 folded into scan3)
    scan1_kernel<<<nb, 1024>>>(cnt, offs, bsum, N);
    scan3_kernel<<<n256, 256>>>(offs, bsum, nb, cnt, cursor, rdeg, N);
    fill_kernel<<<egrid, 256>>>(row, col, cursor, srcs, E);

    // 2) layer 1: h = x @ W1^T + b1   (fp32 x split inline during staging)
    tc_gemm_kernel<true><<<ggrid, 512, SMEM_GEMM_BYTES>>>(
        x, nullptr, whi, wlo, b1, h, N);

    // 3) mp 1: (ahi, alo) = split(relu(mean of in-neighbors of h))
    aggregate_kernel<<<wgrid, 256>>>(h, offs, cnt, srcs, rdeg,
                                     (__nv_bfloat162*)ahi, (__nv_bfloat162*)alo, N);

    // 4) layer 2
    tc_gemm_kernel<false><<<ggrid, 512, SMEM_GEMM_BYTES>>>(
        ahi, alo, whi + DIM * DIM, wlo + DIM * DIM, b2, h, N);

    // 5) mp 2
    aggregate_kernel<<<wgrid, 256>>>(h, offs, cnt, srcs, rdeg,
                                     (__nv_bfloat162*)ahi, (__nv_bfloat162*)alo, N);

    // 6) layer 3: out = agg @ W3^T + b3
    tc_gemm_kernel<false><<<ggrid, 512, SMEM_GEMM_BYTES>>>(
        ahi, alo, whi + 2 * DIM * DIM, wlo + 2 * DIM * DIM, b3, out, N);
}

// round 14
// speedup vs baseline: 1.1998x; 1.0070x over previous
#include <cuda_runtime.h>
#include <cuda_bf16.h>
#include <stdint.h>

typedef unsigned long long u64;

// Problem constants (fixed shapes for this problem)
#define MAXN 100000
#define MAXE 800000
#define DIM  128
#define LD   136   // padded SMEM row stride in bf16 (272B: 16B-aligned, ldmatrix conflict-free)

// Scratch (device globals — no allocation allowed)
__device__ float         g_h[(size_t)MAXN * DIM];      // fp32 activations (GEMM out)
__device__ __nv_bfloat16 g_ahi[(size_t)MAXN * DIM];    // split-bf16 GEMM input (hi)
__device__ __nv_bfloat16 g_alo[(size_t)MAXN * DIM];    // split-bf16 GEMM input (lo)
__device__ __nv_bfloat16 g_whi[3 * DIM * DIM];         // W1/W2/W3 hi
__device__ __nv_bfloat16 g_wlo[3 * DIM * DIM];         // W1/W2/W3 lo
__device__ float g_rdeg[MAXN];
__device__ int   g_row[MAXE];
__device__ int   g_col[MAXE];
__device__ int   g_cnt[MAXN];
__device__ int   g_offs[MAXN];
__device__ int   g_cursor[MAXN];
__device__ int   g_srcs[MAXE];
__device__ int   g_bsum[1024];
__device__ int   g_is32;   // monotone under atomicOr; input-fixed -> never re-zeroed

__device__ __forceinline__ uint32_t smem_u32(const void* p) {
    uint32_t a;
    asm("{ .reg .u64 t; cvta.to.shared.u64 t, %1; cvt.u32.u64 %0, t; }" : "=r"(a) : "l"(p));
    return a;
}

// ---------------------------------------------------------------------------
// fp32 -> split bf16 (hi + lo)
// ---------------------------------------------------------------------------
__device__ __forceinline__ void split2(float a, float b,
                                       __nv_bfloat162& hi, __nv_bfloat162& lo) {
    __nv_bfloat16 ha = __float2bfloat16_rn(a);
    __nv_bfloat16 hb = __float2bfloat16_rn(b);
    hi = __nv_bfloat162(ha, hb);
    lo = __floats2bfloat162_rn(a - __bfloat162float(ha), b - __bfloat162float(hb));
}

// ---------------------------------------------------------------------------
// Fused: zero cnt[] + dtype probe + weight split (all independent).
// ---------------------------------------------------------------------------
__global__ void zero_probe_splitw_kernel(
    const unsigned* __restrict__ w, int E,
    int* __restrict__ cnt, int n,
    int* __restrict__ flag,
    const float4* __restrict__ W1, const float4* __restrict__ W2,
    const float4* __restrict__ W3,
    __nv_bfloat162* __restrict__ whi, __nv_bfloat162* __restrict__ wlo)
{
    int i = blockIdx.x * blockDim.x + threadIdx.x;
    if (i < n) cnt[i] = 0;
    if (i < E) {
        if (w[2 * i + 1] != 0u) atomicOr(flag, 1);
    }
    if (i < 3 * 4096) {
        int layer = i / 4096, j = i % 4096;
        const float4* W = (layer == 0) ? W1 : (layer == 1) ? W2 : W3;
        float4 v = __ldg(W + j);
        __nv_bfloat162 h0, l0, h1, l1;
        split2(v.x, v.y, h0, l0);
        split2(v.z, v.w, h1, l1);
        whi[2 * i] = h0;  whi[2 * i + 1] = h1;
        wlo[2 * i] = l0;  wlo[2 * i + 1] = l1;
    }
}

__global__ void convert_count_kernel(const void* __restrict__ ei,
                                     int* __restrict__ row, int* __restrict__ col,
                                     int* __restrict__ cnt,
                                     int E, const int* __restrict__ flag) {
    int i = blockIdx.x * blockDim.x + threadIdx.x;
    if (i >= E) return;
    int r, c;
    if (*flag) {
        const int* p = (const int*)ei;
        r = p[i];
        c = p[E + i];
    } else {
        const long long* p = (const long long*)ei;
        r = (int)p[i];
        c = (int)p[E + i];
    }
    row[i] = r;
    col[i] = c;
    atomicAdd(&cnt[r], 1);
}

__global__ void scan1_kernel(const int* __restrict__ cnt, int* __restrict__ offs,
                             int* __restrict__ bsum, int n) {
    __shared__ int sh[1024];
    int i = blockIdx.x * 1024 + threadIdx.x;
    int v = (i < n) ? cnt[i] : 0;
    sh[threadIdx.x] = v;
    __syncthreads();
    #pragma unroll
    for (int d = 1; d < 1024; d <<= 1) {
        int t = (threadIdx.x >= d) ? sh[threadIdx.x - d] : 0;
        __syncthreads();
        sh[threadIdx.x] += t;
        __syncthreads();
    }
    if (i < n) offs[i] = sh[threadIdx.x] - v;   // exclusive within block
    if (threadIdx.x == 1023) bsum[blockIdx.x] = sh[1023];
}

// scan3: finalize offsets; re-derives the (<=256-entry) exclusive prefix of
// bsum in SMEM per block (removes the grid=1 scan2 launch).
__global__ void scan3_kernel(int* __restrict__ offs, const int* __restrict__ bsum,
                             int nb,
                             const int* __restrict__ cnt, int* __restrict__ cursor,
                             float* __restrict__ rdeg, int n) {
    __shared__ int sh[256];
    int t = threadIdx.x;
    int v = (t < nb) ? bsum[t] : 0;
    sh[t] = v;
    __syncthreads();
    #pragma unroll
    for (int d = 1; d < 256; d <<= 1) {
        int tv = (t >= d) ? sh[t - d] : 0;
        __syncthreads();
        sh[t] += tv;
        __syncthreads();
    }
    int i = blockIdx.x * 256 + t;
    if (i >= n) return;
    int blk = i >> 10;
    int base = (blk == 0) ? 0 : sh[blk - 1];
    int o = offs[i] + base;
    offs[i] = o;
    cursor[i] = o;
    rdeg[i] = 1.0f / fmaxf((float)cnt[i], 1.0f);
}

__global__ void fill_kernel(const int* __restrict__ row, const int* __restrict__ col,
                            int* __restrict__ cursor, int* __restrict__ srcs, int E) {
    int e = blockIdx.x * blockDim.x + threadIdx.x;
    if (e >= E) return;
    int idx = atomicAdd(&cursor[row[e]], 1);
    srcs[idx] = col[e];
}

// ---------------------------------------------------------------------------
// Pull-mode aggregate: relu(mean of in-neighbors) -> split bf16 (hi, lo)
// ---------------------------------------------------------------------------
__global__ __launch_bounds__(256) void aggregate_kernel(
    const float* __restrict__ h,
    const int* __restrict__ offs,
    const int* __restrict__ cnt,
    const int* __restrict__ srcs,
    const float* __restrict__ rdeg,
    __nv_bfloat162* __restrict__ ahi,
    __nv_bfloat162* __restrict__ alo,
    int N)
{
    int node = blockIdx.x * 8 + (threadIdx.x >> 5);
    if (node >= N) return;
    int lane = threadIdx.x & 31;

    int start = __ldg(offs + node);
    int c     = __ldg(cnt + node);

    float4 acc = make_float4(0.f, 0.f, 0.f, 0.f);
    int j = 0;
    for (; j + 4 <= c; j += 4) {
        int s0 = __ldg(srcs + start + j);
        int s1 = __ldg(srcs + start + j + 1);
        int s2 = __ldg(srcs + start + j + 2);
        int s3 = __ldg(srcs + start + j + 3);
        float4 v0 = __ldg((const float4*)(h + (size_t)s0 * DIM) + lane);
        float4 v1 = __ldg((const float4*)(h + (size_t)s1 * DIM) + lane);
        float4 v2 = __ldg((const float4*)(h + (size_t)s2 * DIM) + lane);
        float4 v3 = __ldg((const float4*)(h + (size_t)s3 * DIM) + lane);
        acc.x += (v0.x + v1.x) + (v2.x + v3.x);
        acc.y += (v0.y + v1.y) + (v2.y + v3.y);
        acc.z += (v0.z + v1.z) + (v2.z + v3.z);
        acc.w += (v0.w + v1.w) + (v2.w + v3.w);
    }
    for (; j < c; ++j) {
        int s0 = __ldg(srcs + start + j);
        float4 v0 = __ldg((const float4*)(h + (size_t)s0 * DIM) + lane);
        acc.x += v0.x;
        acc.y += v0.y;
        acc.z += v0.z;
        acc.w += v0.w;
    }

    float rd = __ldg(rdeg + node);
    float4 o;
    o.x = fmaxf(acc.x * rd, 0.f);
    o.y = fmaxf(acc.y * rd, 0.f);
    o.z = fmaxf(acc.z * rd, 0.f);
    o.w = fmaxf(acc.w * rd, 0.f);

    __nv_bfloat162 h0, l0, h1, l1;
    split2(o.x, o.y, h0, l0);
    split2(o.z, o.w, h1, l1);
    size_t base = (size_t)node * (DIM / 2) + lane * 2;
    ahi[base] = h0;  ahi[base + 1] = h1;
    alo[base] = l0;  alo[base + 1] = l1;
}

// ---------------------------------------------------------------------------
// Tensor-core split-bf16 GEMM via mma.sync (HMMA pipe):
//   out[M,128] = A[M,128] @ W[128,128]^T + bias
//   D = Ahi@Whi + Ahi@Wlo + Alo@Whi  (3 sequential passes, fp32 acc)
// CTA: 128x128, 16 warps (512 threads) 4x4; warp = 32x32 via 2x4 m16n8k16.
// B fragments for 2 adjacent n-tiles loaded with ONE ldmatrix.x4
// (4 8x8 matrices: {nt k0, nt k1, nt+1 k0, nt+1 k1}) -> LDSM/k-step 6 -> 4.
// ---------------------------------------------------------------------------
#define SMEM_TILE (128 * LD)                 // bf16 elements per tile
#define SMEM_GEMM_BYTES (4 * SMEM_TILE * 2)  // 139,264 B

template <bool CONVERT>
__global__ __launch_bounds__(512, 1) void tc_gemm_kernel(
    const void* __restrict__ Asrc,           // CONVERT ? fp32[M,128] : bf16 hi
    const __nv_bfloat16* __restrict__ Alo,   // used when !CONVERT
    const __nv_bfloat16* __restrict__ Whi,
    const __nv_bfloat16* __restrict__ Wlo,
    const float* __restrict__ bias,
    float* __restrict__ out,
    int M)
{
    extern __shared__ __nv_bfloat16 sm[];
    const int tid  = threadIdx.x;
    const int wid  = tid >> 5;
    const int lane = tid & 31;
    const int m0   = blockIdx.x * 128;

    __nv_bfloat16* sAhi = sm;
    __nv_bfloat16* sAlo = sAhi + SMEM_TILE;
    __nv_bfloat16* sWhi = sAlo + SMEM_TILE;
    __nv_bfloat16* sWlo = sWhi + SMEM_TILE;

    // ---- load 4 tiles into padded SMEM (16B chunks; 4 iters/thread) ----
    for (int idx = tid; idx < 2048; idx += 512) {
        int r  = idx >> 4;      // row 0..127
        int ck = idx & 15;      // chunk of 8 bf16 (16B)
        int m  = m0 + r;
        if (CONVERT) {
            const float* x = (const float*)Asrc;
            uint4 hi4 = make_uint4(0, 0, 0, 0), lo4 = hi4;
            if (m < M) {
                float4 va = __ldg((const float4*)(x + (size_t)m * DIM + ck * 8));
                float4 vb = __ldg((const float4*)(x + (size_t)m * DIM + ck * 8) + 1);
                __nv_bfloat162 h0, l0, h1, l1, h2, l2, h3, l3;
                split2(va.x, va.y, h0, l0);
                split2(va.z, va.w, h1, l1);
                split2(vb.x, vb.y, h2, l2);
                split2(vb.z, vb.w, h3, l3);
                hi4 = make_uint4(*(uint32_t*)&h0, *(uint32_t*)&h1,
                                 *(uint32_t*)&h2, *(uint32_t*)&h3);
                lo4 = make_uint4(*(uint32_t*)&l0, *(uint32_t*)&l1,
                                 *(uint32_t*)&l2, *(uint32_t*)&l3);
            }
            *(uint4*)(sAhi + r * LD + ck * 8) = hi4;
            *(uint4*)(sAlo + r * LD + ck * 8) = lo4;
        } else {
            const __nv_bfloat16* Ahi = (const __nv_bfloat16*)Asrc;
            uint4 va = make_uint4(0, 0, 0, 0), vb = va;
            if (m < M) {
                va = __ldg((const uint4*)(Ahi + (size_t)m * DIM) + ck);
                vb = __ldg((const uint4*)(Alo + (size_t)m * DIM) + ck);
            }
            *(uint4*)(sAhi + r * LD + ck * 8) = va;
            *(uint4*)(sAlo + r * LD + ck * 8) = vb;
        }
        uint4 wa = __ldg((const uint4*)(Whi + (size_t)r * DIM) + ck);
        uint4 wb = __ldg((const uint4*)(Wlo + (size_t)r * DIM) + ck);
        *(uint4*)(sWhi + r * LD + ck * 8) = wa;
        *(uint4*)(sWlo + r * LD + ck * 8) = wb;
    }
    __syncthreads();

    const int mw = wid >> 2;          // 0..3
    const int nw = wid & 3;           // 0..3
    const int mBase = mw * 32;
    const int nBase = nw * 32;

    float acc[2][4][4];
    #pragma unroll
    for (int i = 0; i < 2; ++i)
        #pragma unroll
        for (int j = 0; j < 4; ++j)
            #pragma unroll
            for (int q = 0; q < 4; ++q) acc[i][j][q] = 0.f;

    // A x4 ldmatrix: lanes 0-15 -> 16 rows, k-half by lane>>4.
    const uint32_t aRowOff = (uint32_t)(mBase + (lane & 15)) * (LD * 2) + ((lane >> 4) << 4);
    // B x4 ldmatrix (2 n-tiles at once): matrices = {nt k0, nt k1, nt+1 k0, nt+1 k1}
    // lanes 0-7: nt rows k0 | 8-15: nt rows k1 | 16-23: nt+1 rows k0 | 24-31: nt+1 rows k1
    const uint32_t bRowOff = (uint32_t)(nBase + ((lane >> 4) << 3) + (lane & 7)) * (LD * 2)
                             + (((lane >> 3) & 1) << 4);

    const uint32_t sb     = smem_u32(sm);
    const uint32_t offAhi = 0;
    const uint32_t offAlo = SMEM_TILE * 2;
    const uint32_t offWhi = SMEM_TILE * 4;
    const uint32_t offWlo = SMEM_TILE * 6;

    #pragma unroll 1
    for (int pass = 0; pass < 3; ++pass) {
        const uint32_t aBase = sb + ((pass == 2) ? offAlo : offAhi) + aRowOff;
        const uint32_t bBase = sb + ((pass == 1) ? offWlo : offWhi) + bRowOff;

        #pragma unroll 2
        for (int k = 0; k < 8; ++k) {          // k16 steps, +32B each
            uint32_t a[2][4];
            #pragma unroll
            for (int mt = 0; mt < 2; ++mt) {
                uint32_t addr = aBase + (uint32_t)(mt * 16) * (LD * 2) + k * 32;
                asm volatile("ldmatrix.sync.aligned.m8n8.x4.shared.b16 {%0,%1,%2,%3}, [%4];"
                             : "=r"(a[mt][0]), "=r"(a[mt][1]), "=r"(a[mt][2]), "=r"(a[mt][3])
                             : "r"(addr));
            }
            uint32_t b[4][2];
            #pragma unroll
            for (int np = 0; np < 2; ++np) {   // n-tile pair: tiles 2np, 2np+1
                uint32_t addr = bBase + (uint32_t)(np * 16) * (LD * 2) + k * 32;
                asm volatile("ldmatrix.sync.aligned.m8n8.x4.shared.b16 {%0,%1,%2,%3}, [%4];"
                             : "=r"(b[2 * np][0]), "=r"(b[2 * np][1]),
                               "=r"(b[2 * np + 1][0]), "=r"(b[2 * np + 1][1])
                             : "r"(addr));
            }
            #pragma unroll
            for (int mt = 0; mt < 2; ++mt)
                #pragma unroll
                for (int nt = 0; nt < 4; ++nt) {
                    asm volatile(
                        "mma.sync.aligned.m16n8k16.row.col.f32.bf16.bf16.f32 "
                        "{%0,%1,%2,%3}, {%4,%5,%6,%7}, {%8,%9}, {%0,%1,%2,%3};"
                        : "+f"(acc[mt][nt][0]), "+f"(acc[mt][nt][1]),
                          "+f"(acc[mt][nt][2]), "+f"(acc[mt][nt][3])
                        : "r"(a[mt][0]), "r"(a[mt][1]), "r"(a[mt][2]), "r"(a[mt][3]),
                          "r"(b[nt][0]), "r"(b[nt][1]));
                }
        }
    }

    // ---- epilogue: + bias, fp32 store ----
    const int r0 = lane >> 2;           // 0..7
    const int c0 = (lane & 3) * 2;      // 0,2,4,6
    #pragma unroll
    for (int nt = 0; nt < 4; ++nt) {
        int coln = nBase + nt * 8 + c0;
        float2 bv = __ldg((const float2*)(bias + coln));
        #pragma unroll
        for (int mt = 0; mt < 2; ++mt) {
            int row = m0 + mBase + mt * 16 + r0;
            if (row < M) {
                float2 v0 = make_float2(acc[mt][nt][0] + bv.x, acc[mt][nt][1] + bv.y);
                *(float2*)(out + (size_t)row * DIM + coln) = v0;
            }
            if (row + 8 < M) {
                float2 v1 = make_float2(acc[mt][nt][2] + bv.x, acc[mt][nt][3] + bv.y);
                *(float2*)(out + (size_t)(row + 8) * DIM + coln) = v1;
            }
        }
    }
}

// ---------------------------------------------------------------------------
// kernel_launch
// ---------------------------------------------------------------------------
extern "C" void kernel_launch(void* const* d_in, const int* in_sizes, int n_in,
                              void* d_out, int out_size)
{
    const float* x   = (const float*)d_in[0];
    const void*  ei  = d_in[1];
    const float* W1  = (const float*)d_in[2];
    const float* b1  = (const float*)d_in[3];
    const float* W2  = (const float*)d_in[4];
    const float* b2  = (const float*)d_in[5];
    const float* W3  = (const float*)d_in[6];
    const float* b3  = (const float*)d_in[7];
    float*       out = (float*)d_out;

    const int N = in_sizes[0] / DIM;
    const int E = in_sizes[1] / 2;

    float* h;             cudaGetSymbolAddress((void**)&h,      g_h);
    __nv_bfloat16* ahi;   cudaGetSymbolAddress((void**)&ahi,    g_ahi);
    __nv_bfloat16* alo;   cudaGetSymbolAddress((void**)&alo,    g_alo);
    __nv_bfloat16* whi;   cudaGetSymbolAddress((void**)&whi,    g_whi);
    __nv_bfloat16* wlo;   cudaGetSymbolAddress((void**)&wlo,    g_wlo);
    float* rdeg;          cudaGetSymbolAddress((void**)&rdeg,   g_rdeg);
    int*   row;           cudaGetSymbolAddress((void**)&row,    g_row);
    int*   col;           cudaGetSymbolAddress((void**)&col,    g_col);
    int*   cnt;           cudaGetSymbolAddress((void**)&cnt,    g_cnt);
    int*   offs;          cudaGetSymbolAddress((void**)&offs,   g_offs);
    int*   cursor;        cudaGetSymbolAddress((void**)&cursor, g_cursor);
    int*   srcs;          cudaGetSymbolAddress((void**)&srcs,   g_srcs);
    int*   bsum;          cudaGetSymbolAddress((void**)&bsum,   g_bsum);
    int*   flag;          cudaGetSymbolAddress((void**)&flag,   g_is32);

    const int egrid = (E + 255) / 256;
    const int n256  = (N + 255) / 256;
    const int nb    = (N + 1023) / 1024;
    const int wgrid = (N + 7) / 8;
    const int ggrid = (N + 127) / 128;

    cudaFuncSetAttribute(tc_gemm_kernel<true>,
                         cudaFuncAttributeMaxDynamicSharedMemorySize, SMEM_GEMM_BYTES);
    cudaFuncSetAttribute(tc_gemm_kernel<false>,
                         cudaFuncAttributeMaxDynamicSharedMemorySize, SMEM_GEMM_BYTES);

    // 0) prep: zero cnt + probe + split W, then edge normalize + count
    zero_probe_splitw_kernel<<<egrid, 256>>>(
        (const unsigned*)ei, E, cnt, N, flag,
        (const float4*)W1, (const float4*)W2, (const float4*)W3,
        (__nv_bfloat162*)whi, (__nv_bfloat162*)wlo);
    convert_count_kernel<<<egrid, 256>>>(ei, row, col, cnt, E, flag);
    scan1_kernel<<<nb, 1024>>>(cnt, offs, bsum, N);

    // 1) layer 1 moved here (depends only on launch #0): also puts the GEMM
    //    in the ncu capture window (4th launch).
    tc_gemm_kernel<true><<<ggrid, 512, SMEM_GEMM_BYTES>>>(
        x, nullptr, whi, wlo, b1, h, N);

    // 2) finish CSR build
    scan3_kernel<<<n256, 256>>>(offs, bsum, nb, cnt, cursor, rdeg, N);
    fill_kernel<<<egrid, 256>>>(row, col, cursor, srcs, E);

    // 3) mp 1
    aggregate_kernel<<<wgrid, 256>>>(h, offs, cnt, srcs, rdeg,
                                     (__nv_bfloat162*)ahi, (__nv_bfloat162*)alo, N);

    // 4) layer 2
    tc_gemm_kernel<false><<<ggrid, 512, SMEM_GEMM_BYTES>>>(
        ahi, alo, whi + DIM * DIM, wlo + DIM * DIM, b2, h, N);

    // 5) mp 2
    aggregate_kernel<<<wgrid, 256>>>(h, offs, cnt, srcs, rdeg,
                                     (__nv_bfloat162*)ahi, (__nv_bfloat162*)alo, N);

    // 6) layer 3
    tc_gemm_kernel<false><<<ggrid, 512, SMEM_GEMM_BYTES>>>(
        ahi, alo, whi + 2 * DIM * DIM, wlo + 2 * DIM * DIM, b3, out, N);
}

// round 15
// speedup vs baseline: 1.2251x; 1.0211x over previous
#include <cuda_runtime.h>
#include <cuda_bf16.h>
#include <stdint.h>

typedef unsigned long long u64;

// Problem constants (fixed shapes for this problem)
#define MAXN 100000
#define MAXE 800000
#define DIM  128
#define LD   136   // padded SMEM row stride in bf16 (272B: 16B-aligned, ldmatrix conflict-free)

// Scratch (device globals — no allocation allowed)
__device__ float         g_h[(size_t)MAXN * DIM];      // fp32 activations (GEMM out)
__device__ __nv_bfloat16 g_ahi[(size_t)MAXN * DIM];    // split-bf16 GEMM input (hi)
__device__ __nv_bfloat16 g_alo[(size_t)MAXN * DIM];    // split-bf16 GEMM input (lo)
__device__ __nv_bfloat16 g_whi[3 * DIM * DIM];         // W1/W2/W3 hi
__device__ __nv_bfloat16 g_wlo[3 * DIM * DIM];         // W1/W2/W3 lo
__device__ float g_rdeg[MAXN];
__device__ int   g_row[MAXE];
__device__ int   g_col[MAXE];
__device__ int   g_cnt[MAXN];
__device__ int   g_offs[MAXN];
__device__ int   g_cursor[MAXN];
__device__ int   g_srcs[MAXE];
__device__ int   g_bsum[1024];
__device__ int   g_is32;   // monotone under atomicOr; input-fixed -> never re-zeroed

__device__ __forceinline__ uint32_t smem_u32(const void* p) {
    uint32_t a;
    asm("{ .reg .u64 t; cvta.to.shared.u64 t, %1; cvt.u32.u64 %0, t; }" : "=r"(a) : "l"(p));
    return a;
}

// ---------------------------------------------------------------------------
// fp32 -> split bf16 (hi + lo)
// ---------------------------------------------------------------------------
__device__ __forceinline__ void split2(float a, float b,
                                       __nv_bfloat162& hi, __nv_bfloat162& lo) {
    __nv_bfloat16 ha = __float2bfloat16_rn(a);
    __nv_bfloat16 hb = __float2bfloat16_rn(b);
    hi = __nv_bfloat162(ha, hb);
    lo = __floats2bfloat162_rn(a - __bfloat162float(ha), b - __bfloat162float(hb));
}

// ---------------------------------------------------------------------------
// Fused: zero cnt[] + dtype probe + weight split (all independent).
// ---------------------------------------------------------------------------
__global__ void zero_probe_splitw_kernel(
    const unsigned* __restrict__ w, int E,
    int* __restrict__ cnt, int n,
    int* __restrict__ flag,
    const float4* __restrict__ W1, const float4* __restrict__ W2,
    const float4* __restrict__ W3,
    __nv_bfloat162* __restrict__ whi, __nv_bfloat162* __restrict__ wlo)
{
    int i = blockIdx.x * blockDim.x + threadIdx.x;
    if (i < n) cnt[i] = 0;
    if (i < E) {
        if (w[2 * i + 1] != 0u) atomicOr(flag, 1);
    }
    if (i < 3 * 4096) {
        int layer = i / 4096, j = i % 4096;
        const float4* W = (layer == 0) ? W1 : (layer == 1) ? W2 : W3;
        float4 v = __ldg(W + j);
        __nv_bfloat162 h0, l0, h1, l1;
        split2(v.x, v.y, h0, l0);
        split2(v.z, v.w, h1, l1);
        whi[2 * i] = h0;  whi[2 * i + 1] = h1;
        wlo[2 * i] = l0;  wlo[2 * i + 1] = l1;
    }
}

__global__ void convert_count_kernel(const void* __restrict__ ei,
                                     int* __restrict__ row, int* __restrict__ col,
                                     int* __restrict__ cnt,
                                     int E, const int* __restrict__ flag) {
    int i = blockIdx.x * blockDim.x + threadIdx.x;
    if (i >= E) return;
    int r, c;
    if (*flag) {
        const int* p = (const int*)ei;
        r = p[i];
        c = p[E + i];
    } else {
        const long long* p = (const long long*)ei;
        r = (int)p[i];
        c = (int)p[E + i];
    }
    row[i] = r;
    col[i] = c;
    atomicAdd(&cnt[r], 1);
}

__global__ void scan1_kernel(const int* __restrict__ cnt, int* __restrict__ offs,
                             int* __restrict__ bsum, int n) {
    __shared__ int sh[1024];
    int i = blockIdx.x * 1024 + threadIdx.x;
    int v = (i < n) ? cnt[i] : 0;
    sh[threadIdx.x] = v;
    __syncthreads();
    #pragma unroll
    for (int d = 1; d < 1024; d <<= 1) {
        int t = (threadIdx.x >= d) ? sh[threadIdx.x - d] : 0;
        __syncthreads();
        sh[threadIdx.x] += t;
        __syncthreads();
    }
    if (i < n) offs[i] = sh[threadIdx.x] - v;   // exclusive within block
    if (threadIdx.x == 1023) bsum[blockIdx.x] = sh[1023];
}

// scan3: finalize offsets; re-derives the (<=256-entry) exclusive prefix of
// bsum in SMEM per block (removes the grid=1 scan2 launch).
__global__ void scan3_kernel(int* __restrict__ offs, const int* __restrict__ bsum,
                             int nb,
                             const int* __restrict__ cnt, int* __restrict__ cursor,
                             float* __restrict__ rdeg, int n) {
    __shared__ int sh[256];
    int t = threadIdx.x;
    int v = (t < nb) ? bsum[t] : 0;
    sh[t] = v;
    __syncthreads();
    #pragma unroll
    for (int d = 1; d < 256; d <<= 1) {
        int tv = (t >= d) ? sh[t - d] : 0;
        __syncthreads();
        sh[t] += tv;
        __syncthreads();
    }
    int i = blockIdx.x * 256 + t;
    if (i >= n) return;
    int blk = i >> 10;
    int base = (blk == 0) ? 0 : sh[blk - 1];
    int o = offs[i] + base;
    offs[i] = o;
    cursor[i] = o;
    rdeg[i] = 1.0f / fmaxf((float)cnt[i], 1.0f);
}

__global__ void fill_kernel(const int* __restrict__ row, const int* __restrict__ col,
                            int* __restrict__ cursor, int* __restrict__ srcs, int E) {
    int e = blockIdx.x * blockDim.x + threadIdx.x;
    if (e >= E) return;
    int idx = atomicAdd(&cursor[row[e]], 1);
    srcs[idx] = col[e];
}

// ---------------------------------------------------------------------------
// Pull-mode aggregate: relu(mean of in-neighbors) -> split bf16 (hi, lo)
// ---------------------------------------------------------------------------
__global__ __launch_bounds__(256) void aggregate_kernel(
    const float* __restrict__ h,
    const int* __restrict__ offs,
    const int* __restrict__ cnt,
    const int* __restrict__ srcs,
    const float* __restrict__ rdeg,
    __nv_bfloat162* __restrict__ ahi,
    __nv_bfloat162* __restrict__ alo,
    int N)
{
    int node = blockIdx.x * 8 + (threadIdx.x >> 5);
    if (node >= N) return;
    int lane = threadIdx.x & 31;

    int start = __ldg(offs + node);
    int c     = __ldg(cnt + node);

    float4 acc = make_float4(0.f, 0.f, 0.f, 0.f);
    int j = 0;
    for (; j + 4 <= c; j += 4) {
        int s0 = __ldg(srcs + start + j);
        int s1 = __ldg(srcs + start + j + 1);
        int s2 = __ldg(srcs + start + j + 2);
        int s3 = __ldg(srcs + start + j + 3);
        float4 v0 = __ldg((const float4*)(h + (size_t)s0 * DIM) + lane);
        float4 v1 = __ldg((const float4*)(h + (size_t)s1 * DIM) + lane);
        float4 v2 = __ldg((const float4*)(h + (size_t)s2 * DIM) + lane);
        float4 v3 = __ldg((const float4*)(h + (size_t)s3 * DIM) + lane);
        acc.x += (v0.x + v1.x) + (v2.x + v3.x);
        acc.y += (v0.y + v1.y) + (v2.y + v3.y);
        acc.z += (v0.z + v1.z) + (v2.z + v3.z);
        acc.w += (v0.w + v1.w) + (v2.w + v3.w);
    }
    for (; j < c; ++j) {
        int s0 = __ldg(srcs + start + j);
        float4 v0 = __ldg((const float4*)(h + (size_t)s0 * DIM) + lane);
        acc.x += v0.x;
        acc.y += v0.y;
        acc.z += v0.z;
        acc.w += v0.w;
    }

    float rd = __ldg(rdeg + node);
    float4 o;
    o.x = fmaxf(acc.x * rd, 0.f);
    o.y = fmaxf(acc.y * rd, 0.f);
    o.z = fmaxf(acc.z * rd, 0.f);
    o.w = fmaxf(acc.w * rd, 0.f);

    __nv_bfloat162 h0, l0, h1, l1;
    split2(o.x, o.y, h0, l0);
    split2(o.z, o.w, h1, l1);
    size_t base = (size_t)node * (DIM / 2) + lane * 2;
    ahi[base] = h0;  ahi[base + 1] = h1;
    alo[base] = l0;  alo[base + 1] = l1;
}

// ---------------------------------------------------------------------------
// Tensor-core split-bf16 GEMM via mma.sync (HMMA pipe):
//   out[M,128] = A[M,128] @ W[128,128]^T + bias
//   D = Ahi@Whi + Ahi@Wlo + Alo@Whi  — FULLY FUSED single k-loop: each
//   fragment (ah/al/bh/bl) is ldmatrix'd ONCE per k-step and reused by
//   3 MMAs -> LDSM per warp 96 -> 64 (attacks the measured 57% L1 pipe).
//   Safe at 16 warps/32x32 tiles: acc=32 regs + 32 fragment regs (~94 total).
// CTA: 128x128, 16 warps (512 threads) 4x4; warp = 32x32 via 2x4 m16n8k16.
// B fragments for 2 adjacent n-tiles loaded with ONE ldmatrix.x4.
// ---------------------------------------------------------------------------
#define SMEM_TILE (128 * LD)                 // bf16 elements per tile
#define SMEM_GEMM_BYTES (4 * SMEM_TILE * 2)  // 139,264 B

template <bool CONVERT>
__global__ __launch_bounds__(512, 1) void tc_gemm_kernel(
    const void* __restrict__ Asrc,           // CONVERT ? fp32[M,128] : bf16 hi
    const __nv_bfloat16* __restrict__ Alo,   // used when !CONVERT
    const __nv_bfloat16* __restrict__ Whi,
    const __nv_bfloat16* __restrict__ Wlo,
    const float* __restrict__ bias,
    float* __restrict__ out,
    int M)
{
    extern __shared__ __nv_bfloat16 sm[];
    const int tid  = threadIdx.x;
    const int wid  = tid >> 5;
    const int lane = tid & 31;
    const int m0   = blockIdx.x * 128;

    __nv_bfloat16* sAhi = sm;
    __nv_bfloat16* sAlo = sAhi + SMEM_TILE;
    __nv_bfloat16* sWhi = sAlo + SMEM_TILE;
    __nv_bfloat16* sWlo = sWhi + SMEM_TILE;

    // ---- load 4 tiles into padded SMEM (16B chunks; 4 iters/thread) ----
    for (int idx = tid; idx < 2048; idx += 512) {
        int r  = idx >> 4;      // row 0..127
        int ck = idx & 15;      // chunk of 8 bf16 (16B)
        int m  = m0 + r;
        if (CONVERT) {
            const float* x = (const float*)Asrc;
            uint4 hi4 = make_uint4(0, 0, 0, 0), lo4 = hi4;
            if (m < M) {
                float4 va = __ldg((const float4*)(x + (size_t)m * DIM + ck * 8));
                float4 vb = __ldg((const float4*)(x + (size_t)m * DIM + ck * 8) + 1);
                __nv_bfloat162 h0, l0, h1, l1, h2, l2, h3, l3;
                split2(va.x, va.y, h0, l0);
                split2(va.z, va.w, h1, l1);
                split2(vb.x, vb.y, h2, l2);
                split2(vb.z, vb.w, h3, l3);
                hi4 = make_uint4(*(uint32_t*)&h0, *(uint32_t*)&h1,
                                 *(uint32_t*)&h2, *(uint32_t*)&h3);
                lo4 = make_uint4(*(uint32_t*)&l0, *(uint32_t*)&l1,
                                 *(uint32_t*)&l2, *(uint32_t*)&l3);
            }
            *(uint4*)(sAhi + r * LD + ck * 8) = hi4;
            *(uint4*)(sAlo + r * LD + ck * 8) = lo4;
        } else {
            const __nv_bfloat16* Ahi = (const __nv_bfloat16*)Asrc;
            uint4 va = make_uint4(0, 0, 0, 0), vb = va;
            if (m < M) {
                va = __ldg((const uint4*)(Ahi + (size_t)m * DIM) + ck);
                vb = __ldg((const uint4*)(Alo + (size_t)m * DIM) + ck);
            }
            *(uint4*)(sAhi + r * LD + ck * 8) = va;
            *(uint4*)(sAlo + r * LD + ck * 8) = vb;
        }
        uint4 wa = __ldg((const uint4*)(Whi + (size_t)r * DIM) + ck);
        uint4 wb = __ldg((const uint4*)(Wlo + (size_t)r * DIM) + ck);
        *(uint4*)(sWhi + r * LD + ck * 8) = wa;
        *(uint4*)(sWlo + r * LD + ck * 8) = wb;
    }
    __syncthreads();

    const int mw = wid >> 2;          // 0..3
    const int nw = wid & 3;           // 0..3
    const int mBase = mw * 32;
    const int nBase = nw * 32;

    float acc[2][4][4];
    #pragma unroll
    for (int i = 0; i < 2; ++i)
        #pragma unroll
        for (int j = 0; j < 4; ++j)
            #pragma unroll
            for (int q = 0; q < 4; ++q) acc[i][j][q] = 0.f;

    // A x4 ldmatrix: lanes 0-15 -> 16 rows, k-half by lane>>4.
    const uint32_t aRowOff = (uint32_t)(mBase + (lane & 15)) * (LD * 2) + ((lane >> 4) << 4);
    // B x4 ldmatrix (2 n-tiles at once): matrices = {nt k0, nt k1, nt+1 k0, nt+1 k1}
    const uint32_t bRowOff = (uint32_t)(nBase + ((lane >> 4) << 3) + (lane & 7)) * (LD * 2)
                             + (((lane >> 3) & 1) << 4);

    const uint32_t sb   = smem_u32(sm);
    const uint32_t aHiB = sb + aRowOff;
    const uint32_t aLoB = sb + SMEM_TILE * 2 + aRowOff;
    const uint32_t bHiB = sb + SMEM_TILE * 4 + bRowOff;
    const uint32_t bLoB = sb + SMEM_TILE * 6 + bRowOff;

    #pragma unroll 2
    for (int k = 0; k < 8; ++k) {          // k16 steps, +32B each
        const uint32_t kb = (uint32_t)k * 32;
        uint32_t ah[2][4], al[2][4];
        #pragma unroll
        for (int mt = 0; mt < 2; ++mt) {
            uint32_t off = (uint32_t)(mt * 16) * (LD * 2) + kb;
            asm volatile("ldmatrix.sync.aligned.m8n8.x4.shared.b16 {%0,%1,%2,%3}, [%4];"
                         : "=r"(ah[mt][0]), "=r"(ah[mt][1]), "=r"(ah[mt][2]), "=r"(ah[mt][3])
                         : "r"(aHiB + off));
            asm volatile("ldmatrix.sync.aligned.m8n8.x4.shared.b16 {%0,%1,%2,%3}, [%4];"
                         : "=r"(al[mt][0]), "=r"(al[mt][1]), "=r"(al[mt][2]), "=r"(al[mt][3])
                         : "r"(aLoB + off));
        }
        uint32_t bh[4][2], bl[4][2];
        #pragma unroll
        for (int np = 0; np < 2; ++np) {   // n-tile pair: tiles 2np, 2np+1
            uint32_t off = (uint32_t)(np * 16) * (LD * 2) + kb;
            asm volatile("ldmatrix.sync.aligned.m8n8.x4.shared.b16 {%0,%1,%2,%3}, [%4];"
                         : "=r"(bh[2 * np][0]), "=r"(bh[2 * np][1]),
                           "=r"(bh[2 * np + 1][0]), "=r"(bh[2 * np + 1][1])
                         : "r"(bHiB + off));
            asm volatile("ldmatrix.sync.aligned.m8n8.x4.shared.b16 {%0,%1,%2,%3}, [%4];"
                         : "=r"(bl[2 * np][0]), "=r"(bl[2 * np][1]),
                           "=r"(bl[2 * np + 1][0]), "=r"(bl[2 * np + 1][1])
                         : "r"(bLoB + off));
        }
        #pragma unroll
        for (int mt = 0; mt < 2; ++mt)
            #pragma unroll
            for (int nt = 0; nt < 4; ++nt) {
                asm volatile(
                    "mma.sync.aligned.m16n8k16.row.col.f32.bf16.bf16.f32 "
                    "{%0,%1,%2,%3}, {%4,%5,%6,%7}, {%8,%9}, {%0,%1,%2,%3};"
                    : "+f"(acc[mt][nt][0]), "+f"(acc[mt][nt][1]),
                      "+f"(acc[mt][nt][2]), "+f"(acc[mt][nt][3])
                    : "r"(ah[mt][0]), "r"(ah[mt][1]), "r"(ah[mt][2]), "r"(ah[mt][3]),
                      "r"(bh[nt][0]), "r"(bh[nt][1]));
                asm volatile(
                    "mma.sync.aligned.m16n8k16.row.col.f32.bf16.bf16.f32 "
                    "{%0,%1,%2,%3}, {%4,%5,%6,%7}, {%8,%9}, {%0,%1,%2,%3};"
                    : "+f"(acc[mt][nt][0]), "+f"(acc[mt][nt][1]),
                      "+f"(acc[mt][nt][2]), "+f"(acc[mt][nt][3])
                    : "r"(ah[mt][0]), "r"(ah[mt][1]), "r"(ah[mt][2]), "r"(ah[mt][3]),
                      "r"(bl[nt][0]), "r"(bl[nt][1]));
                asm volatile(
                    "mma.sync.aligned.m16n8k16.row.col.f32.bf16.bf16.f32 "
                    "{%0,%1,%2,%3}, {%4,%5,%6,%7}, {%8,%9}, {%0,%1,%2,%3};"
                    : "+f"(acc[mt][nt][0]), "+f"(acc[mt][nt][1]),
                      "+f"(acc[mt][nt][2]), "+f"(acc[mt][nt][3])
                    : "r"(al[mt][0]), "r"(al[mt][1]), "r"(al[mt][2]), "r"(al[mt][3]),
                      "r"(bh[nt][0]), "r"(bh[nt][1]));
            }
    }

    // ---- epilogue: + bias, fp32 store ----
    const int r0 = lane >> 2;           // 0..7
    const int c0 = (lane & 3) * 2;      // 0,2,4,6
    #pragma unroll
    for (int nt = 0; nt < 4; ++nt) {
        int coln = nBase + nt * 8 + c0;
        float2 bv = __ldg((const float2*)(bias + coln));
        #pragma unroll
        for (int mt = 0; mt < 2; ++mt) {
            int row = m0 + mBase + mt * 16 + r0;
            if (row < M) {
                float2 v0 = make_float2(acc[mt][nt][0] + bv.x, acc[mt][nt][1] + bv.y);
                *(float2*)(out + (size_t)row * DIM + coln) = v0;
            }
            if (row + 8 < M) {
                float2 v1 = make_float2(acc[mt][nt][2] + bv.x, acc[mt][nt][3] + bv.y);
                *(float2*)(out + (size_t)(row + 8) * DIM + coln) = v1;
            }
        }
    }
}

// ---------------------------------------------------------------------------
// kernel_launch
// ---------------------------------------------------------------------------
extern "C" void kernel_launch(void* const* d_in, const int* in_sizes, int n_in,
                              void* d_out, int out_size)
{
    const float* x   = (const float*)d_in[0];
    const void*  ei  = d_in[1];
    const float* W1  = (const float*)d_in[2];
    const float* b1  = (const float*)d_in[3];
    const float* W2  = (const float*)d_in[4];
    const float* b2  = (const float*)d_in[5];
    const float* W3  = (const float*)d_in[6];
    const float* b3  = (const float*)d_in[7];
    float*       out = (float*)d_out;

    const int N = in_sizes[0] / DIM;
    const int E = in_sizes[1] / 2;

    float* h;             cudaGetSymbolAddress((void**)&h,      g_h);
    __nv_bfloat16* ahi;   cudaGetSymbolAddress((void**)&ahi,    g_ahi);
    __nv_bfloat16* alo;   cudaGetSymbolAddress((void**)&alo,    g_alo);
    __nv_bfloat16* whi;   cudaGetSymbolAddress((void**)&whi,    g_whi);
    __nv_bfloat16* wlo;   cudaGetSymbolAddress((void**)&wlo,    g_wlo);
    float* rdeg;          cudaGetSymbolAddress((void**)&rdeg,   g_rdeg);
    int*   row;           cudaGetSymbolAddress((void**)&row,    g_row);
    int*   col;           cudaGetSymbolAddress((void**)&col,    g_col);
    int*   cnt;           cudaGetSymbolAddress((void**)&cnt,    g_cnt);
    int*   offs;          cudaGetSymbolAddress((void**)&offs,   g_offs);
    int*   cursor;        cudaGetSymbolAddress((void**)&cursor, g_cursor);
    int*   srcs;          cudaGetSymbolAddress((void**)&srcs,   g_srcs);
    int*   bsum;          cudaGetSymbolAddress((void**)&bsum,   g_bsum);
    int*   flag;          cudaGetSymbolAddress((void**)&flag,   g_is32);

    const int egrid = (E + 255) / 256;
    const int n256  = (N + 255) / 256;
    const int nb    = (N + 1023) / 1024;
    const int wgrid = (N + 7) / 8;
    const int ggrid = (N + 127) / 128;

    cudaFuncSetAttribute(tc_gemm_kernel<true>,
                         cudaFuncAttributeMaxDynamicSharedMemorySize, SMEM_GEMM_BYTES);
    cudaFuncSetAttribute(tc_gemm_kernel<false>,
                         cudaFuncAttributeMaxDynamicSharedMemorySize, SMEM_GEMM_BYTES);

    // 0) prep: zero cnt + probe + split W, then edge normalize + count
    zero_probe_splitw_kernel<<<egrid, 256>>>(
        (const unsigned*)ei, E, cnt, N, flag,
        (const float4*)W1, (const float4*)W2, (const float4*)W3,
        (__nv_bfloat162*)whi, (__nv_bfloat162*)wlo);
    convert_count_kernel<<<egrid, 256>>>(ei, row, col, cnt, E, flag);
    scan1_kernel<<<nb, 1024>>>(cnt, offs, bsum, N);

    // 1) layer 1 (only needs launch #0's whi/wlo) — 4th launch for ncu window
    tc_gemm_kernel<true><<<ggrid, 512, SMEM_GEMM_BYTES>>>(
        x, nullptr, whi, wlo, b1, h, N);

    // 2) finish CSR build
    scan3_kernel<<<n256, 256>>>(offs, bsum, nb, cnt, cursor, rdeg, N);
    fill_kernel<<<egrid, 256>>>(row, col, cursor, srcs, E);

    // 3) mp 1
    aggregate_kernel<<<wgrid, 256>>>(h, offs, cnt, srcs, rdeg,
                                     (__nv_bfloat162*)ahi, (__nv_bfloat162*)alo, N);

    // 4) layer 2
    tc_gemm_kernel<false><<<ggrid, 512, SMEM_GEMM_BYTES>>>(
        ahi, alo, whi + DIM * DIM, wlo + DIM * DIM, b2, h, N);

    // 5) mp 2
    aggregate_kernel<<<wgrid, 256>>>(h, offs, cnt, srcs, rdeg,
                                     (__nv_bfloat162*)ahi, (__nv_bfloat162*)alo, N);

    // 6) layer 3
    tc_gemm_kernel<false><<<ggrid, 512, SMEM_GEMM_BYTES>>>(
        ahi, alo, whi + 2 * DIM * DIM, wlo + 2 * DIM * DIM, b3, out, N);
}

// round 16
// speedup vs baseline: 1.2339x; 1.0072x over previous
#include <cuda_runtime.h>
#include <cuda_bf16.h>
#include <stdint.h>

typedef unsigned long long u64;

// Problem constants (fixed shapes for this problem)
#define MAXN 100000
#define MAXE 800000
#define DIM  128
#define LD   136   // padded SMEM row stride in bf16 (272B: 16B-aligned, ldmatrix conflict-free)

// Scratch (device globals — no allocation allowed)
__device__ float         g_h[(size_t)MAXN * DIM];      // fp32 activations (GEMM out)
__device__ __nv_bfloat16 g_ahi[(size_t)MAXN * DIM];    // split-bf16 GEMM input (hi)
__device__ __nv_bfloat16 g_alo[(size_t)MAXN * DIM];    // split-bf16 GEMM input (lo)
__device__ __nv_bfloat16 g_whi[3 * DIM * DIM];         // W1/W2/W3 hi
__device__ __nv_bfloat16 g_wlo[3 * DIM * DIM];         // W1/W2/W3 lo
__device__ float g_rdeg[MAXN];
__device__ int   g_row[MAXE];
__device__ int   g_col[MAXE];
__device__ int   g_cnt[MAXN];
__device__ int   g_offs[MAXN];
__device__ int   g_cursor[MAXN];
__device__ int   g_srcs[MAXE];
__device__ int   g_bsum[1024];
__device__ int   g_is32;   // monotone under atomicOr; input-fixed -> never re-zeroed

__device__ __forceinline__ uint32_t smem_u32(const void* p) {
    uint32_t a;
    asm("{ .reg .u64 t; cvta.to.shared.u64 t, %1; cvt.u32.u64 %0, t; }" : "=r"(a) : "l"(p));
    return a;
}

// cp.async helpers (sm_80+ base ISA): 16B copy, optional zero-fill via src-size
#define CP_ASYNC16(dst, src, srcsz) \
    asm volatile("cp.async.cg.shared.global [%0], [%1], 16, %2;" \
                 :: "r"(dst), "l"(src), "r"(srcsz))
#define CP_ASYNC_COMMIT() asm volatile("cp.async.commit_group;" ::: "memory")
#define CP_ASYNC_WAIT0()  asm volatile("cp.async.wait_group 0;" ::: "memory")

// ---------------------------------------------------------------------------
// fp32 -> split bf16 (hi + lo)
// ---------------------------------------------------------------------------
__device__ __forceinline__ void split2(float a, float b,
                                       __nv_bfloat162& hi, __nv_bfloat162& lo) {
    __nv_bfloat16 ha = __float2bfloat16_rn(a);
    __nv_bfloat16 hb = __float2bfloat16_rn(b);
    hi = __nv_bfloat162(ha, hb);
    lo = __floats2bfloat162_rn(a - __bfloat162float(ha), b - __bfloat162float(hb));
}

// ---------------------------------------------------------------------------
// Fused: zero cnt[] + dtype probe + weight split (all independent).
// ---------------------------------------------------------------------------
__global__ void zero_probe_splitw_kernel(
    const unsigned* __restrict__ w, int E,
    int* __restrict__ cnt, int n,
    int* __restrict__ flag,
    const float4* __restrict__ W1, const float4* __restrict__ W2,
    const float4* __restrict__ W3,
    __nv_bfloat162* __restrict__ whi, __nv_bfloat162* __restrict__ wlo)
{
    int i = blockIdx.x * blockDim.x + threadIdx.x;
    if (i < n) cnt[i] = 0;
    if (i < E) {
        if (w[2 * i + 1] != 0u) atomicOr(flag, 1);
    }
    if (i < 3 * 4096) {
        int layer = i / 4096, j = i % 4096;
        const float4* W = (layer == 0) ? W1 : (layer == 1) ? W2 : W3;
        float4 v = __ldg(W + j);
        __nv_bfloat162 h0, l0, h1, l1;
        split2(v.x, v.y, h0, l0);
        split2(v.z, v.w, h1, l1);
        whi[2 * i] = h0;  whi[2 * i + 1] = h1;
        wlo[2 * i] = l0;  wlo[2 * i + 1] = l1;
    }
}

__global__ void convert_count_kernel(const void* __restrict__ ei,
                                     int* __restrict__ row, int* __restrict__ col,
                                     int* __restrict__ cnt,
                                     int E, const int* __restrict__ flag) {
    int i = blockIdx.x * blockDim.x + threadIdx.x;
    if (i >= E) return;
    int r, c;
    if (*flag) {
        const int* p = (const int*)ei;
        r = p[i];
        c = p[E + i];
    } else {
        const long long* p = (const long long*)ei;
        r = (int)p[i];
        c = (int)p[E + i];
    }
    row[i] = r;
    col[i] = c;
    atomicAdd(&cnt[r], 1);
}

__global__ void scan1_kernel(const int* __restrict__ cnt, int* __restrict__ offs,
                             int* __restrict__ bsum, int n) {
    __shared__ int sh[1024];
    int i = blockIdx.x * 1024 + threadIdx.x;
    int v = (i < n) ? cnt[i] : 0;
    sh[threadIdx.x] = v;
    __syncthreads();
    #pragma unroll
    for (int d = 1; d < 1024; d <<= 1) {
        int t = (threadIdx.x >= d) ? sh[threadIdx.x - d] : 0;
        __syncthreads();
        sh[threadIdx.x] += t;
        __syncthreads();
    }
    if (i < n) offs[i] = sh[threadIdx.x] - v;   // exclusive within block
    if (threadIdx.x == 1023) bsum[blockIdx.x] = sh[1023];
}

// scan3: finalize offsets; re-derives the (<=256-entry) exclusive prefix of
// bsum in SMEM per block (removes the grid=1 scan2 launch).
__global__ void scan3_kernel(int* __restrict__ offs, const int* __restrict__ bsum,
                             int nb,
                             const int* __restrict__ cnt, int* __restrict__ cursor,
                             float* __restrict__ rdeg, int n) {
    __shared__ int sh[256];
    int t = threadIdx.x;
    int v = (t < nb) ? bsum[t] : 0;
    sh[t] = v;
    __syncthreads();
    #pragma unroll
    for (int d = 1; d < 256; d <<= 1) {
        int tv = (t >= d) ? sh[t - d] : 0;
        __syncthreads();
        sh[t] += tv;
        __syncthreads();
    }
    int i = blockIdx.x * 256 + t;
    if (i >= n) return;
    int blk = i >> 10;
    int base = (blk == 0) ? 0 : sh[blk - 1];
    int o = offs[i] + base;
    offs[i] = o;
    cursor[i] = o;
    rdeg[i] = 1.0f / fmaxf((float)cnt[i], 1.0f);
}

__global__ void fill_kernel(const int* __restrict__ row, const int* __restrict__ col,
                            int* __restrict__ cursor, int* __restrict__ srcs, int E) {
    int e = blockIdx.x * blockDim.x + threadIdx.x;
    if (e >= E) return;
    int idx = atomicAdd(&cursor[row[e]], 1);
    srcs[idx] = col[e];
}

// ---------------------------------------------------------------------------
// Pull-mode aggregate: relu(mean of in-neighbors) -> split bf16 (hi, lo)
// ---------------------------------------------------------------------------
__global__ __launch_bounds__(256) void aggregate_kernel(
    const float* __restrict__ h,
    const int* __restrict__ offs,
    const int* __restrict__ cnt,
    const int* __restrict__ srcs,
    const float* __restrict__ rdeg,
    __nv_bfloat162* __restrict__ ahi,
    __nv_bfloat162* __restrict__ alo,
    int N)
{
    int node = blockIdx.x * 8 + (threadIdx.x >> 5);
    if (node >= N) return;
    int lane = threadIdx.x & 31;

    int start = __ldg(offs + node);
    int c     = __ldg(cnt + node);

    float4 acc = make_float4(0.f, 0.f, 0.f, 0.f);
    int j = 0;
    for (; j + 4 <= c; j += 4) {
        int s0 = __ldg(srcs + start + j);
        int s1 = __ldg(srcs + start + j + 1);
        int s2 = __ldg(srcs + start + j + 2);
        int s3 = __ldg(srcs + start + j + 3);
        float4 v0 = __ldg((const float4*)(h + (size_t)s0 * DIM) + lane);
        float4 v1 = __ldg((const float4*)(h + (size_t)s1 * DIM) + lane);
        float4 v2 = __ldg((const float4*)(h + (size_t)s2 * DIM) + lane);
        float4 v3 = __ldg((const float4*)(h + (size_t)s3 * DIM) + lane);
        acc.x += (v0.x + v1.x) + (v2.x + v3.x);
        acc.y += (v0.y + v1.y) + (v2.y + v3.y);
        acc.z += (v0.z + v1.z) + (v2.z + v3.z);
        acc.w += (v0.w + v1.w) + (v2.w + v3.w);
    }
    for (; j < c; ++j) {
        int s0 = __ldg(srcs + start + j);
        float4 v0 = __ldg((const float4*)(h + (size_t)s0 * DIM) + lane);
        acc.x += v0.x;
        acc.y += v0.y;
        acc.z += v0.z;
        acc.w += v0.w;
    }

    float rd = __ldg(rdeg + node);
    float4 o;
    o.x = fmaxf(acc.x * rd, 0.f);
    o.y = fmaxf(acc.y * rd, 0.f);
    o.z = fmaxf(acc.z * rd, 0.f);
    o.w = fmaxf(acc.w * rd, 0.f);

    __nv_bfloat162 h0, l0, h1, l1;
    split2(o.x, o.y, h0, l0);
    split2(o.z, o.w, h1, l1);
    size_t base = (size_t)node * (DIM / 2) + lane * 2;
    ahi[base] = h0;  ahi[base + 1] = h1;
    alo[base] = l0;  alo[base + 1] = l1;
}

// ---------------------------------------------------------------------------
// Tensor-core split-bf16 GEMM via mma.sync (HMMA pipe):
//   out[M,128] = A[M,128] @ W[128,128]^T + bias
//   D = Ahi@Whi + Ahi@Wlo + Alo@Whi  — fully fused single k-loop.
// Staging via cp.async (LDGSTS): no register roundtrip, deep MLP, zero-fill
// for OOB rows. Layer-1 A keeps the LDG+split path (needs fp32 transform).
// CTA: 128x128, 16 warps (512 threads) 4x4; warp = 32x32 via 2x4 m16n8k16.
// ---------------------------------------------------------------------------
#define SMEM_TILE (128 * LD)                 // bf16 elements per tile
#define SMEM_GEMM_BYTES (4 * SMEM_TILE * 2)  // 139,264 B

template <bool CONVERT>
__global__ __launch_bounds__(512, 1) void tc_gemm_kernel(
    const void* __restrict__ Asrc,           // CONVERT ? fp32[M,128] : bf16 hi
    const __nv_bfloat16* __restrict__ Alo,   // used when !CONVERT
    const __nv_bfloat16* __restrict__ Whi,
    const __nv_bfloat16* __restrict__ Wlo,
    const float* __restrict__ bias,
    float* __restrict__ out,
    int M)
{
    extern __shared__ __nv_bfloat16 sm[];
    const int tid  = threadIdx.x;
    const int wid  = tid >> 5;
    const int lane = tid & 31;
    const int m0   = blockIdx.x * 128;

    __nv_bfloat16* sAhi = sm;
    __nv_bfloat16* sAlo = sAhi + SMEM_TILE;

    const uint32_t sb = smem_u32(sm);
    const uint32_t sbAhi = sb;
    const uint32_t sbAlo = sb + SMEM_TILE * 2;
    const uint32_t sbWhi = sb + SMEM_TILE * 4;
    const uint32_t sbWlo = sb + SMEM_TILE * 6;

    // ---- stage tiles via cp.async (4 iters/thread) ----
    for (int idx = tid; idx < 2048; idx += 512) {
        int r  = idx >> 4;      // row 0..127
        int ck = idx & 15;      // chunk of 8 bf16 (16B)
        int m  = m0 + r;
        uint32_t soff = (uint32_t)(r * LD + ck * 8) * 2;   // byte offset in a tile

        // W tiles: always in-bounds
        CP_ASYNC16(sbWhi + soff, (const char*)(Whi + (size_t)r * DIM) + ck * 16, 16);
        CP_ASYNC16(sbWlo + soff, (const char*)(Wlo + (size_t)r * DIM) + ck * 16, 16);

        if (CONVERT) {
            // fp32 A -> split bf16 (register path; transform required)
            const float* x = (const float*)Asrc;
            uint4 hi4 = make_uint4(0, 0, 0, 0), lo4 = hi4;
            if (m < M) {
                float4 va = __ldg((const float4*)(x + (size_t)m * DIM + ck * 8));
                float4 vb = __ldg((const float4*)(x + (size_t)m * DIM + ck * 8) + 1);
                __nv_bfloat162 h0, l0, h1, l1, h2, l2, h3, l3;
                split2(va.x, va.y, h0, l0);
                split2(va.z, va.w, h1, l1);
                split2(vb.x, vb.y, h2, l2);
                split2(vb.z, vb.w, h3, l3);
                hi4 = make_uint4(*(uint32_t*)&h0, *(uint32_t*)&h1,
                                 *(uint32_t*)&h2, *(uint32_t*)&h3);
                lo4 = make_uint4(*(uint32_t*)&l0, *(uint32_t*)&l1,
                                 *(uint32_t*)&l2, *(uint32_t*)&l3);
            }
            *(uint4*)(sAhi + r * LD + ck * 8) = hi4;
            *(uint4*)(sAlo + r * LD + ck * 8) = lo4;
        } else {
            const __nv_bfloat16* Ahi = (const __nv_bfloat16*)Asrc;
            int sz = (m < M) ? 16 : 0;   // zero-fill OOB rows
            CP_ASYNC16(sbAhi + soff, (const char*)(Ahi + (size_t)m * DIM) + ck * 16, sz);
            CP_ASYNC16(sbAlo + soff, (const char*)(Alo + (size_t)m * DIM) + ck * 16, sz);
        }
    }
    CP_ASYNC_COMMIT();
    CP_ASYNC_WAIT0();
    __syncthreads();

    const int mw = wid >> 2;          // 0..3
    const int nw = wid & 3;           // 0..3
    const int mBase = mw * 32;
    const int nBase = nw * 32;

    float acc[2][4][4];
    #pragma unroll
    for (int i = 0; i < 2; ++i)
        #pragma unroll
        for (int j = 0; j < 4; ++j)
            #pragma unroll
            for (int q = 0; q < 4; ++q) acc[i][j][q] = 0.f;

    // A x4 ldmatrix: lanes 0-15 -> 16 rows, k-half by lane>>4.
    const uint32_t aRowOff = (uint32_t)(mBase + (lane & 15)) * (LD * 2) + ((lane >> 4) << 4);
    // B x4 ldmatrix (2 n-tiles at once): matrices = {nt k0, nt k1, nt+1 k0, nt+1 k1}
    const uint32_t bRowOff = (uint32_t)(nBase + ((lane >> 4) << 3) + (lane & 7)) * (LD * 2)
                             + (((lane >> 3) & 1) << 4);

    const uint32_t aHiB = sbAhi + aRowOff;
    const uint32_t aLoB = sbAlo + aRowOff;
    const uint32_t bHiB = sbWhi + bRowOff;
    const uint32_t bLoB = sbWlo + bRowOff;

    #pragma unroll 4
    for (int k = 0; k < 8; ++k) {          // k16 steps, +32B each
        const uint32_t kb = (uint32_t)k * 32;
        uint32_t ah[2][4], al[2][4];
        #pragma unroll
        for (int mt = 0; mt < 2; ++mt) {
            uint32_t off = (uint32_t)(mt * 16) * (LD * 2) + kb;
            asm volatile("ldmatrix.sync.aligned.m8n8.x4.shared.b16 {%0,%1,%2,%3}, [%4];"
                         : "=r"(ah[mt][0]), "=r"(ah[mt][1]), "=r"(ah[mt][2]), "=r"(ah[mt][3])
                         : "r"(aHiB + off));
            asm volatile("ldmatrix.sync.aligned.m8n8.x4.shared.b16 {%0,%1,%2,%3}, [%4];"
                         : "=r"(al[mt][0]), "=r"(al[mt][1]), "=r"(al[mt][2]), "=r"(al[mt][3])
                         : "r"(aLoB + off));
        }
        uint32_t bh[4][2], bl[4][2];
        #pragma unroll
        for (int np = 0; np < 2; ++np) {   // n-tile pair: tiles 2np, 2np+1
            uint32_t off = (uint32_t)(np * 16) * (LD * 2) + kb;
            asm volatile("ldmatrix.sync.aligned.m8n8.x4.shared.b16 {%0,%1,%2,%3}, [%4];"
                         : "=r"(bh[2 * np][0]), "=r"(bh[2 * np][1]),
                           "=r"(bh[2 * np + 1][0]), "=r"(bh[2 * np + 1][1])
                         : "r"(bHiB + off));
            asm volatile("ldmatrix.sync.aligned.m8n8.x4.shared.b16 {%0,%1,%2,%3}, [%4];"
                         : "=r"(bl[2 * np][0]), "=r"(bl[2 * np][1]),
                           "=r"(bl[2 * np + 1][0]), "=r"(bl[2 * np + 1][1])
                         : "r"(bLoB + off));
        }
        #pragma unroll
        for (int mt = 0; mt < 2; ++mt)
            #pragma unroll
            for (int nt = 0; nt < 4; ++nt) {
                asm volatile(
                    "mma.sync.aligned.m16n8k16.row.col.f32.bf16.bf16.f32 "
                    "{%0,%1,%2,%3}, {%4,%5,%6,%7}, {%8,%9}, {%0,%1,%2,%3};"
                    : "+f"(acc[mt][nt][0]), "+f"(acc[mt][nt][1]),
                      "+f"(acc[mt][nt][2]), "+f"(acc[mt][nt][3])
                    : "r"(ah[mt][0]), "r"(ah[mt][1]), "r"(ah[mt][2]), "r"(ah[mt][3]),
                      "r"(bh[nt][0]), "r"(bh[nt][1]));
                asm volatile(
                    "mma.sync.aligned.m16n8k16.row.col.f32.bf16.bf16.f32 "
                    "{%0,%1,%2,%3}, {%4,%5,%6,%7}, {%8,%9}, {%0,%1,%2,%3};"
                    : "+f"(acc[mt][nt][0]), "+f"(acc[mt][nt][1]),
                      "+f"(acc[mt][nt][2]), "+f"(acc[mt][nt][3])
                    : "r"(ah[mt][0]), "r"(ah[mt][1]), "r"(ah[mt][2]), "r"(ah[mt][3]),
                      "r"(bl[nt][0]), "r"(bl[nt][1]));
                asm volatile(
                    "mma.sync.aligned.m16n8k16.row.col.f32.bf16.bf16.f32 "
                    "{%0,%1,%2,%3}, {%4,%5,%6,%7}, {%8,%9}, {%0,%1,%2,%3};"
                    : "+f"(acc[mt][nt][0]), "+f"(acc[mt][nt][1]),
                      "+f"(acc[mt][nt][2]), "+f"(acc[mt][nt][3])
                    : "r"(al[mt][0]), "r"(al[mt][1]), "r"(al[mt][2]), "r"(al[mt][3]),
                      "r"(bh[nt][0]), "r"(bh[nt][1]));
            }
    }

    // ---- epilogue: + bias, fp32 store ----
    const int r0 = lane >> 2;           // 0..7
    const int c0 = (lane & 3) * 2;      // 0,2,4,6
    #pragma unroll
    for (int nt = 0; nt < 4; ++nt) {
        int coln = nBase + nt * 8 + c0;
        float2 bv = __ldg((const float2*)(bias + coln));
        #pragma unroll
        for (int mt = 0; mt < 2; ++mt) {
            int row = m0 + mBase + mt * 16 + r0;
            if (row < M) {
                float2 v0 = make_float2(acc[mt][nt][0] + bv.x, acc[mt][nt][1] + bv.y);
                *(float2*)(out + (size_t)row * DIM + coln) = v0;
            }
            if (row + 8 < M) {
                float2 v1 = make_float2(acc[mt][nt][2] + bv.x, acc[mt][nt][3] + bv.y);
                *(float2*)(out + (size_t)(row + 8) * DIM + coln) = v1;
            }
        }
    }
}

// ---------------------------------------------------------------------------
// kernel_launch
// ---------------------------------------------------------------------------
extern "C" void kernel_launch(void* const* d_in, const int* in_sizes, int n_in,
                              void* d_out, int out_size)
{
    const float* x   = (const float*)d_in[0];
    const void*  ei  = d_in[1];
    const float* W1  = (const float*)d_in[2];
    const float* b1  = (const float*)d_in[3];
    const float* W2  = (const float*)d_in[4];
    const float* b2  = (const float*)d_in[5];
    const float* W3  = (const float*)d_in[6];
    const float* b3  = (const float*)d_in[7];
    float*       out = (float*)d_out;

    const int N = in_sizes[0] / DIM;
    const int E = in_sizes[1] / 2;

    float* h;             cudaGetSymbolAddress((void**)&h,      g_h);
    __nv_bfloat16* ahi;   cudaGetSymbolAddress((void**)&ahi,    g_ahi);
    __nv_bfloat16* alo;   cudaGetSymbolAddress((void**)&alo,    g_alo);
    __nv_bfloat16* whi;   cudaGetSymbolAddress((void**)&whi,    g_whi);
    __nv_bfloat16* wlo;   cudaGetSymbolAddress((void**)&wlo,    g_wlo);
    float* rdeg;          cudaGetSymbolAddress((void**)&rdeg,   g_rdeg);
    int*   row;           cudaGetSymbolAddress((void**)&row,    g_row);
    int*   col;           cudaGetSymbolAddress((void**)&col,    g_col);
    int*   cnt;           cudaGetSymbolAddress((void**)&cnt,    g_cnt);
    int*   offs;          cudaGetSymbolAddress((void**)&offs,   g_offs);
    int*   cursor;        cudaGetSymbolAddress((void**)&cursor, g_cursor);
    int*   srcs;          cudaGetSymbolAddress((void**)&srcs,   g_srcs);
    int*   bsum;          cudaGetSymbolAddress((void**)&bsum,   g_bsum);
    int*   flag;          cudaGetSymbolAddress((void**)&flag,   g_is32);

    const int egrid = (E + 255) / 256;
    const int n256  = (N + 255) / 256;
    const int nb    = (N + 1023) / 1024;
    const int wgrid = (N + 7) / 8;
    const int ggrid = (N + 127) / 128;

    cudaFuncSetAttribute(tc_gemm_kernel<true>,
                         cudaFuncAttributeMaxDynamicSharedMemorySize, SMEM_GEMM_BYTES);
    cudaFuncSetAttribute(tc_gemm_kernel<false>,
                         cudaFuncAttributeMaxDynamicSharedMemorySize, SMEM_GEMM_BYTES);

    // 0) prep: zero cnt + probe + split W, then edge normalize + count
    zero_probe_splitw_kernel<<<egrid, 256>>>(
        (const unsigned*)ei, E, cnt, N, flag,
        (const float4*)W1, (const float4*)W2, (const float4*)W3,
        (__nv_bfloat162*)whi, (__nv_bfloat162*)wlo);
    convert_count_kernel<<<egrid, 256>>>(ei, row, col, cnt, E, flag);
    scan1_kernel<<<nb, 1024>>>(cnt, offs, bsum, N);

    // 1) layer 1 (only needs launch #0's whi/wlo) — 4th launch for ncu window
    tc_gemm_kernel<true><<<ggrid, 512, SMEM_GEMM_BYTES>>>(
        x, nullptr, whi, wlo, b1, h, N);

    // 2) finish CSR build
    scan3_kernel<<<n256, 256>>>(offs, bsum, nb, cnt, cursor, rdeg, N);
    fill_kernel<<<egrid, 256>>>(row, col, cursor, srcs, E);

    // 3) mp 1
    aggregate_kernel<<<wgrid, 256>>>(h, offs, cnt, srcs, rdeg,
                                     (__nv_bfloat162*)ahi, (__nv_bfloat162*)alo, N);

    // 4) layer 2
    tc_gemm_kernel<false><<<ggrid, 512, SMEM_GEMM_BYTES>>>(
        ahi, alo, whi + DIM * DIM, wlo + DIM * DIM, b2, h, N);

    // 5) mp 2
    aggregate_kernel<<<wgrid, 256>>>(h, offs, cnt, srcs, rdeg,
                                     (__nv_bfloat162*)ahi, (__nv_bfloat162*)alo, N);

    // 6) layer 3
    tc_gemm_kernel<false><<<ggrid, 512, SMEM_GEMM_BYTES>>>(
        ahi, alo, whi + 2 * DIM * DIM, wlo + 2 * DIM * DIM, b3, out, N);
}

// round 17
// speedup vs baseline: 1.3323x; 1.0797x over previous
#include <cuda_runtime.h>
#include <cuda_bf16.h>
#include <stdint.h>

typedef unsigned long long u64;

// Problem constants (fixed shapes for this problem)
#define MAXN 100000
#define MAXE 800000
#define DIM  128
#define LD   136   // padded SMEM row stride in bf16 (272B: 16B-aligned, ldmatrix conflict-free)

// Scratch (device globals — no allocation allowed)
__device__ float         g_h[(size_t)MAXN * DIM];      // fp32 activations (GEMM out)
__device__ __nv_bfloat16 g_ahi[(size_t)MAXN * DIM];    // split-bf16 GEMM input (hi)
__device__ __nv_bfloat16 g_alo[(size_t)MAXN * DIM];    // split-bf16 GEMM input (lo)
__device__ __nv_bfloat16 g_whi[3 * DIM * DIM];         // W1/W2/W3 hi
__device__ __nv_bfloat16 g_wlo[3 * DIM * DIM];         // W1/W2/W3 lo
__device__ float g_rdeg[MAXN];
__device__ int   g_row[MAXE];
__device__ int   g_col[MAXE];
__device__ int   g_cnt[MAXN];
__device__ int   g_offs[MAXN];
__device__ int   g_cursor[MAXN];
__device__ int   g_srcs[MAXE];
__device__ int   g_bsum[1024];
__device__ int   g_is32;   // monotone under atomicOr; input-fixed -> never re-zeroed

__device__ __forceinline__ uint32_t smem_u32(const void* p) {
    uint32_t a;
    asm("{ .reg .u64 t; cvta.to.shared.u64 t, %1; cvt.u32.u64 %0, t; }" : "=r"(a) : "l"(p));
    return a;
}

// cp.async helpers (sm_80+ base ISA): 16B copy, optional zero-fill via src-size
#define CP_ASYNC16(dst, src, srcsz) \
    asm volatile("cp.async.cg.shared.global [%0], [%1], 16, %2;" \
                 :: "r"(dst), "l"(src), "r"(srcsz))
#define CP_ASYNC_COMMIT() asm volatile("cp.async.commit_group;" ::: "memory")
#define CP_ASYNC_WAIT0()  asm volatile("cp.async.wait_group 0;" ::: "memory")

// ---------------------------------------------------------------------------
// fp32 -> split bf16 (hi + lo)
// ---------------------------------------------------------------------------
__device__ __forceinline__ void split2(float a, float b,
                                       __nv_bfloat162& hi, __nv_bfloat162& lo) {
    __nv_bfloat16 ha = __float2bfloat16_rn(a);
    __nv_bfloat16 hb = __float2bfloat16_rn(b);
    hi = __nv_bfloat162(ha, hb);
    lo = __floats2bfloat162_rn(a - __bfloat162float(ha), b - __bfloat162float(hb));
}

// ---------------------------------------------------------------------------
// Fused: zero cnt[] + dtype probe + weight split (all independent).
// ---------------------------------------------------------------------------
__global__ void zero_probe_splitw_kernel(
    const unsigned* __restrict__ w, int E,
    int* __restrict__ cnt, int n,
    int* __restrict__ flag,
    const float4* __restrict__ W1, const float4* __restrict__ W2,
    const float4* __restrict__ W3,
    __nv_bfloat162* __restrict__ whi, __nv_bfloat162* __restrict__ wlo)
{
    int i = blockIdx.x * blockDim.x + threadIdx.x;
    if (i < n) cnt[i] = 0;
    if (i < E) {
        if (w[2 * i + 1] != 0u) atomicOr(flag, 1);
    }
    if (i < 3 * 4096) {
        int layer = i / 4096, j = i % 4096;
        const float4* W = (layer == 0) ? W1 : (layer == 1) ? W2 : W3;
        float4 v = __ldg(W + j);
        __nv_bfloat162 h0, l0, h1, l1;
        split2(v.x, v.y, h0, l0);
        split2(v.z, v.w, h1, l1);
        whi[2 * i] = h0;  whi[2 * i + 1] = h1;
        wlo[2 * i] = l0;  wlo[2 * i + 1] = l1;
    }
}

__global__ void convert_count_kernel(const void* __restrict__ ei,
                                     int* __restrict__ row, int* __restrict__ col,
                                     int* __restrict__ cnt,
                                     int E, const int* __restrict__ flag) {
    int i = blockIdx.x * blockDim.x + threadIdx.x;
    if (i >= E) return;
    int r, c;
    if (*flag) {
        const int* p = (const int*)ei;
        r = p[i];
        c = p[E + i];
    } else {
        const long long* p = (const long long*)ei;
        r = (int)p[i];
        c = (int)p[E + i];
    }
    row[i] = r;
    col[i] = c;
    atomicAdd(&cnt[r], 1);
}

__global__ void scan1_kernel(const int* __restrict__ cnt, int* __restrict__ offs,
                             int* __restrict__ bsum, int n) {
    __shared__ int sh[1024];
    int i = blockIdx.x * 1024 + threadIdx.x;
    int v = (i < n) ? cnt[i] : 0;
    sh[threadIdx.x] = v;
    __syncthreads();
    #pragma unroll
    for (int d = 1; d < 1024; d <<= 1) {
        int t = (threadIdx.x >= d) ? sh[threadIdx.x - d] : 0;
        __syncthreads();
        sh[threadIdx.x] += t;
        __syncthreads();
    }
    if (i < n) offs[i] = sh[threadIdx.x] - v;   // exclusive within block
    if (threadIdx.x == 1023) bsum[blockIdx.x] = sh[1023];
}

// scan3: finalize offsets; re-derives the (<=256-entry) exclusive prefix of
// bsum in SMEM per block (removes the grid=1 scan2 launch).
__global__ void scan3_kernel(int* __restrict__ offs, const int* __restrict__ bsum,
                             int nb,
                             const int* __restrict__ cnt, int* __restrict__ cursor,
                             float* __restrict__ rdeg, int n) {
    __shared__ int sh[256];
    int t = threadIdx.x;
    int v = (t < nb) ? bsum[t] : 0;
    sh[t] = v;
    __syncthreads();
    #pragma unroll
    for (int d = 1; d < 256; d <<= 1) {
        int tv = (t >= d) ? sh[t - d] : 0;
        __syncthreads();
        sh[t] += tv;
        __syncthreads();
    }
    int i = blockIdx.x * 256 + t;
    if (i >= n) return;
    int blk = i >> 10;
    int base = (blk == 0) ? 0 : sh[blk - 1];
    int o = offs[i] + base;
    offs[i] = o;
    cursor[i] = o;
    rdeg[i] = 1.0f / fmaxf((float)cnt[i], 1.0f);
}

__global__ void fill_kernel(const int* __restrict__ row, const int* __restrict__ col,
                            int* __restrict__ cursor, int* __restrict__ srcs, int E) {
    int e = blockIdx.x * blockDim.x + threadIdx.x;
    if (e >= E) return;
    int idx = atomicAdd(&cursor[row[e]], 1);
    srcs[idx] = col[e];
}

// ---------------------------------------------------------------------------
// Pull-mode aggregate: relu(mean of in-neighbors) -> split bf16 (hi, lo)
// ---------------------------------------------------------------------------
__global__ __launch_bounds__(256) void aggregate_kernel(
    const float* __restrict__ h,
    const int* __restrict__ offs,
    const int* __restrict__ cnt,
    const int* __restrict__ srcs,
    const float* __restrict__ rdeg,
    __nv_bfloat162* __restrict__ ahi,
    __nv_bfloat162* __restrict__ alo,
    int N)
{
    int node = blockIdx.x * 8 + (threadIdx.x >> 5);
    if (node >= N) return;
    int lane = threadIdx.x & 31;

    int start = __ldg(offs + node);
    int c     = __ldg(cnt + node);

    float4 acc = make_float4(0.f, 0.f, 0.f, 0.f);
    int j = 0;
    for (; j + 4 <= c; j += 4) {
        int s0 = __ldg(srcs + start + j);
        int s1 = __ldg(srcs + start + j + 1);
        int s2 = __ldg(srcs + start + j + 2);
        int s3 = __ldg(srcs + start + j + 3);
        float4 v0 = __ldg((const float4*)(h + (size_t)s0 * DIM) + lane);
        float4 v1 = __ldg((const float4*)(h + (size_t)s1 * DIM) + lane);
        float4 v2 = __ldg((const float4*)(h + (size_t)s2 * DIM) + lane);
        float4 v3 = __ldg((const float4*)(h + (size_t)s3 * DIM) + lane);
        acc.x += (v0.x + v1.x) + (v2.x + v3.x);
        acc.y += (v0.y + v1.y) + (v2.y + v3.y);
        acc.z += (v0.z + v1.z) + (v2.z + v3.z);
        acc.w += (v0.w + v1.w) + (v2.w + v3.w);
    }
    for (; j < c; ++j) {
        int s0 = __ldg(srcs + start + j);
        float4 v0 = __ldg((const float4*)(h + (size_t)s0 * DIM) + lane);
        acc.x += v0.x;
        acc.y += v0.y;
        acc.z += v0.z;
        acc.w += v0.w;
    }

    float rd = __ldg(rdeg + node);
    float4 o;
    o.x = fmaxf(acc.x * rd, 0.f);
    o.y = fmaxf(acc.y * rd, 0.f);
    o.z = fmaxf(acc.z * rd, 0.f);
    o.w = fmaxf(acc.w * rd, 0.f);

    __nv_bfloat162 h0, l0, h1, l1;
    split2(o.x, o.y, h0, l0);
    split2(o.z, o.w, h1, l1);
    size_t base = (size_t)node * (DIM / 2) + lane * 2;
    ahi[base] = h0;  ahi[base + 1] = h1;
    alo[base] = l0;  alo[base + 1] = l1;
}

// ---------------------------------------------------------------------------
// Tensor-core split-bf16 GEMM via mma.sync (HMMA pipe), 3-buffer / 2-phase:
//   Phase 1: acc = Ahi@Whi + Ahi@Wlo      (buffers: A=Ahi, Whi, Wlo)
//   restage: Alo -> Wlo buffer            (no extra global traffic vs before)
//   Phase 2: acc += Alo@Whi
// SMEM = 3 tiles = 104,448 B  and  __launch_bounds__(512, 2)  -> 2 CTAs/SM:
// one CTA's staging/epilogue overlaps the other's MMA (fixes the measured
// 23% occupancy / latency exposure at zero redundant traffic).
// CTA: 128x128, 16 warps 4x4; warp = 32x32 via 2x4 m16n8k16.
// ---------------------------------------------------------------------------
#define SMEM_TILE (128 * LD)                 // bf16 elements per tile
#define SMEM_GEMM_BYTES (3 * SMEM_TILE * 2)  // 104,448 B

template <bool CONVERT>
__global__ __launch_bounds__(512, 2) void tc_gemm_kernel(
    const void* __restrict__ Asrc,           // CONVERT ? fp32[M,128] : bf16 hi
    const __nv_bfloat16* __restrict__ Alo,   // used when !CONVERT
    const __nv_bfloat16* __restrict__ Whi,
    const __nv_bfloat16* __restrict__ Wlo,
    const float* __restrict__ bias,
    float* __restrict__ out,
    int M)
{
    extern __shared__ __nv_bfloat16 sm[];
    const int tid  = threadIdx.x;
    const int wid  = tid >> 5;
    const int lane = tid & 31;
    const int m0   = blockIdx.x * 128;

    __nv_bfloat16* sA  = sm;                    // Ahi (phase 1), stays
    __nv_bfloat16* sW2 = sm + 2 * SMEM_TILE;    // Wlo (phase 1) -> Alo (phase 2)

    const uint32_t sb   = smem_u32(sm);
    const uint32_t sbA  = sb;
    const uint32_t sbWh = sb + SMEM_TILE * 2;
    const uint32_t sbW2 = sb + SMEM_TILE * 4;

    // ---- stage Ahi, Whi, Wlo ----
    for (int idx = tid; idx < 2048; idx += 512) {
        int r  = idx >> 4;
        int ck = idx & 15;
        int m  = m0 + r;
        uint32_t soff = (uint32_t)(r * LD + ck * 8) * 2;

        CP_ASYNC16(sbWh + soff, (const char*)(Whi + (size_t)r * DIM) + ck * 16, 16);
        CP_ASYNC16(sbW2 + soff, (const char*)(Wlo + (size_t)r * DIM) + ck * 16, 16);

        if (CONVERT) {
            const float* x = (const float*)Asrc;
            uint4 hi4 = make_uint4(0, 0, 0, 0);
            if (m < M) {
                float4 va = __ldg((const float4*)(x + (size_t)m * DIM + ck * 8));
                float4 vb = __ldg((const float4*)(x + (size_t)m * DIM + ck * 8) + 1);
                __nv_bfloat162 h0, l0, h1, l1, h2, l2, h3, l3;
                split2(va.x, va.y, h0, l0);
                split2(va.z, va.w, h1, l1);
                split2(vb.x, vb.y, h2, l2);
                split2(vb.z, vb.w, h3, l3);
                hi4 = make_uint4(*(uint32_t*)&h0, *(uint32_t*)&h1,
                                 *(uint32_t*)&h2, *(uint32_t*)&h3);
            }
            *(uint4*)(sA + r * LD + ck * 8) = hi4;
        } else {
            const __nv_bfloat16* Ahi = (const __nv_bfloat16*)Asrc;
            int sz = (m < M) ? 16 : 0;
            CP_ASYNC16(sbA + soff, (const char*)(Ahi + (size_t)m * DIM) + ck * 16, sz);
        }
    }
    CP_ASYNC_COMMIT();
    CP_ASYNC_WAIT0();
    __syncthreads();

    const int mw = wid >> 2;
    const int nw = wid & 3;
    const int mBase = mw * 32;
    const int nBase = nw * 32;

    float acc[2][4][4];
    #pragma unroll
    for (int i = 0; i < 2; ++i)
        #pragma unroll
        for (int j = 0; j < 4; ++j)
            #pragma unroll
            for (int q = 0; q < 4; ++q) acc[i][j][q] = 0.f;

    const uint32_t aRowOff = (uint32_t)(mBase + (lane & 15)) * (LD * 2) + ((lane >> 4) << 4);
    const uint32_t bRowOff = (uint32_t)(nBase + ((lane >> 4) << 3) + (lane & 7)) * (LD * 2)
                             + (((lane >> 3) & 1) << 4);

    // ---- phase 1: acc = Ahi@Whi + Ahi@Wlo ----
    {
        const uint32_t aB  = sbA  + aRowOff;
        const uint32_t bhB = sbWh + bRowOff;
        const uint32_t blB = sbW2 + bRowOff;
        #pragma unroll 2
        for (int k = 0; k < 8; ++k) {
            const uint32_t kb = (uint32_t)k * 32;
            uint32_t ah[2][4];
            #pragma unroll
            for (int mt = 0; mt < 2; ++mt) {
                uint32_t off = (uint32_t)(mt * 16) * (LD * 2) + kb;
                asm volatile("ldmatrix.sync.aligned.m8n8.x4.shared.b16 {%0,%1,%2,%3}, [%4];"
                             : "=r"(ah[mt][0]), "=r"(ah[mt][1]), "=r"(ah[mt][2]), "=r"(ah[mt][3])
                             : "r"(aB + off));
            }
            uint32_t bh[4][2], bl[4][2];
            #pragma unroll
            for (int np = 0; np < 2; ++np) {
                uint32_t off = (uint32_t)(np * 16) * (LD * 2) + kb;
                asm volatile("ldmatrix.sync.aligned.m8n8.x4.shared.b16 {%0,%1,%2,%3}, [%4];"
                             : "=r"(bh[2 * np][0]), "=r"(bh[2 * np][1]),
                               "=r"(bh[2 * np + 1][0]), "=r"(bh[2 * np + 1][1])
                             : "r"(bhB + off));
                asm volatile("ldmatrix.sync.aligned.m8n8.x4.shared.b16 {%0,%1,%2,%3}, [%4];"
                             : "=r"(bl[2 * np][0]), "=r"(bl[2 * np][1]),
                               "=r"(bl[2 * np + 1][0]), "=r"(bl[2 * np + 1][1])
                             : "r"(blB + off));
            }
            #pragma unroll
            for (int mt = 0; mt < 2; ++mt)
                #pragma unroll
                for (int nt = 0; nt < 4; ++nt) {
                    asm volatile(
                        "mma.sync.aligned.m16n8k16.row.col.f32.bf16.bf16.f32 "
                        "{%0,%1,%2,%3}, {%4,%5,%6,%7}, {%8,%9}, {%0,%1,%2,%3};"
                        : "+f"(acc[mt][nt][0]), "+f"(acc[mt][nt][1]),
                          "+f"(acc[mt][nt][2]), "+f"(acc[mt][nt][3])
                        : "r"(ah[mt][0]), "r"(ah[mt][1]), "r"(ah[mt][2]), "r"(ah[mt][3]),
                          "r"(bh[nt][0]), "r"(bh[nt][1]));
                    asm volatile(
                        "mma.sync.aligned.m16n8k16.row.col.f32.bf16.bf16.f32 "
                        "{%0,%1,%2,%3}, {%4,%5,%6,%7}, {%8,%9}, {%0,%1,%2,%3};"
                        : "+f"(acc[mt][nt][0]), "+f"(acc[mt][nt][1]),
                          "+f"(acc[mt][nt][2]), "+f"(acc[mt][nt][3])
                        : "r"(ah[mt][0]), "r"(ah[mt][1]), "r"(ah[mt][2]), "r"(ah[mt][3]),
                          "r"(bl[nt][0]), "r"(bl[nt][1]));
                }
        }
    }
    __syncthreads();   // all warps done reading Wlo buffer

    // ---- restage: Alo -> W2 buffer ----
    for (int idx = tid; idx < 2048; idx += 512) {
        int r  = idx >> 4;
        int ck = idx & 15;
        int m  = m0 + r;
        uint32_t soff = (uint32_t)(r * LD + ck * 8) * 2;
        if (CONVERT) {
            const float* x = (const float*)Asrc;
            uint4 lo4 = make_uint4(0, 0, 0, 0);
            if (m < M) {
                float4 va = __ldg((const float4*)(x + (size_t)m * DIM + ck * 8));
                float4 vb = __ldg((const float4*)(x + (size_t)m * DIM + ck * 8) + 1);
                __nv_bfloat162 h0, l0, h1, l1, h2, l2, h3, l3;
                split2(va.x, va.y, h0, l0);
                split2(va.z, va.w, h1, l1);
                split2(vb.x, vb.y, h2, l2);
                split2(vb.z, vb.w, h3, l3);
                lo4 = make_uint4(*(uint32_t*)&l0, *(uint32_t*)&l1,
                                 *(uint32_t*)&l2, *(uint32_t*)&l3);
            }
            *(uint4*)(sW2 + r * LD + ck * 8) = lo4;
        } else {
            int sz = (m < M) ? 16 : 0;
            CP_ASYNC16(sbW2 + soff, (const char*)(Alo + (size_t)m * DIM) + ck * 16, sz);
        }
    }
    CP_ASYNC_COMMIT();
    CP_ASYNC_WAIT0();
    __syncthreads();

    // ---- phase 2: acc += Alo@Whi ----
    {
        const uint32_t aB  = sbW2 + aRowOff;
        const uint32_t bhB = sbWh + bRowOff;
        #pragma unroll 2
        for (int k = 0; k < 8; ++k) {
            const uint32_t kb = (uint32_t)k * 32;
            uint32_t al[2][4];
            #pragma unroll
            for (int mt = 0; mt < 2; ++mt) {
                uint32_t off = (uint32_t)(mt * 16) * (LD * 2) + kb;
                asm volatile("ldmatrix.sync.aligned.m8n8.x4.shared.b16 {%0,%1,%2,%3}, [%4];"
                             : "=r"(al[mt][0]), "=r"(al[mt][1]), "=r"(al[mt][2]), "=r"(al[mt][3])
                             : "r"(aB + off));
            }
            uint32_t bh[4][2];
            #pragma unroll
            for (int np = 0; np < 2; ++np) {
                uint32_t off = (uint32_t)(np * 16) * (LD * 2) + kb;
                asm volatile("ldmatrix.sync.aligned.m8n8.x4.shared.b16 {%0,%1,%2,%3}, [%4];"
                             : "=r"(bh[2 * np][0]), "=r"(bh[2 * np][1]),
                               "=r"(bh[2 * np + 1][0]), "=r"(bh[2 * np + 1][1])
                             : "r"(bhB + off));
            }
            #pragma unroll
            for (int mt = 0; mt < 2; ++mt)
                #pragma unroll
                for (int nt = 0; nt < 4; ++nt) {
                    asm volatile(
                        "mma.sync.aligned.m16n8k16.row.col.f32.bf16.bf16.f32 "
                        "{%0,%1,%2,%3}, {%4,%5,%6,%7}, {%8,%9}, {%0,%1,%2,%3};"
                        : "+f"(acc[mt][nt][0]), "+f"(acc[mt][nt][1]),
                          "+f"(acc[mt][nt][2]), "+f"(acc[mt][nt][3])
                        : "r"(al[mt][0]), "r"(al[mt][1]), "r"(al[mt][2]), "r"(al[mt][3]),
                          "r"(bh[nt][0]), "r"(bh[nt][1]));
                }
        }
    }

    // ---- epilogue: + bias, fp32 store ----
    const int r0 = lane >> 2;
    const int c0 = (lane & 3) * 2;
    #pragma unroll
    for (int nt = 0; nt < 4; ++nt) {
        int coln = nBase + nt * 8 + c0;
        float2 bv = __ldg((const float2*)(bias + coln));
        #pragma unroll
        for (int mt = 0; mt < 2; ++mt) {
            int row = m0 + mBase + mt * 16 + r0;
            if (row < M) {
                float2 v0 = make_float2(acc[mt][nt][0] + bv.x, acc[mt][nt][1] + bv.y);
                *(float2*)(out + (size_t)row * DIM + coln) = v0;
            }
            if (row + 8 < M) {
                float2 v1 = make_float2(acc[mt][nt][2] + bv.x, acc[mt][nt][3] + bv.y);
                *(float2*)(out + (size_t)(row + 8) * DIM + coln) = v1;
            }
        }
    }
}

// ---------------------------------------------------------------------------
// kernel_launch
// ---------------------------------------------------------------------------
extern "C" void kernel_launch(void* const* d_in, const int* in_sizes, int n_in,
                              void* d_out, int out_size)
{
    const float* x   = (const float*)d_in[0];
    const void*  ei  = d_in[1];
    const float* W1  = (const float*)d_in[2];
    const float* b1  = (const float*)d_in[3];
    const float* W2  = (const float*)d_in[4];
    const float* b2  = (const float*)d_in[5];
    const float* W3  = (const float*)d_in[6];
    const float* b3  = (const float*)d_in[7];
    float*       out = (float*)d_out;

    const int N = in_sizes[0] / DIM;
    const int E = in_sizes[1] / 2;

    float* h;             cudaGetSymbolAddress((void**)&h,      g_h);
    __nv_bfloat16* ahi;   cudaGetSymbolAddress((void**)&ahi,    g_ahi);
    __nv_bfloat16* alo;   cudaGetSymbolAddress((void**)&alo,    g_alo);
    __nv_bfloat16* whi;   cudaGetSymbolAddress((void**)&whi,    g_whi);
    __nv_bfloat16* wlo;   cudaGetSymbolAddress((void**)&wlo,    g_wlo);
    float* rdeg;          cudaGetSymbolAddress((void**)&rdeg,   g_rdeg);
    int*   row;           cudaGetSymbolAddress((void**)&row,    g_row);
    int*   col;           cudaGetSymbolAddress((void**)&col,    g_col);
    int*   cnt;           cudaGetSymbolAddress((void**)&cnt,    g_cnt);
    int*   offs;          cudaGetSymbolAddress((void**)&offs,   g_offs);
    int*   cursor;        cudaGetSymbolAddress((void**)&cursor, g_cursor);
    int*   srcs;          cudaGetSymbolAddress((void**)&srcs,   g_srcs);
    int*   bsum;          cudaGetSymbolAddress((void**)&bsum,   g_bsum);
    int*   flag;          cudaGetSymbolAddress((void**)&flag,   g_is32);

    const int egrid = (E + 255) / 256;
    const int n256  = (N + 255) / 256;
    const int nb    = (N + 1023) / 1024;
    const int wgrid = (N + 7) / 8;
    const int ggrid = (N + 127) / 128;

    cudaFuncSetAttribute(tc_gemm_kernel<true>,
                         cudaFuncAttributeMaxDynamicSharedMemorySize, SMEM_GEMM_BYTES);
    cudaFuncSetAttribute(tc_gemm_kernel<false>,
                         cudaFuncAttributeMaxDynamicSharedMemorySize, SMEM_GEMM_BYTES);

    // 0) prep: zero cnt + probe + split W, then edge normalize + count
    zero_probe_splitw_kernel<<<egrid, 256>>>(
        (const unsigned*)ei, E, cnt, N, flag,
        (const float4*)W1, (const float4*)W2, (const float4*)W3,
        (__nv_bfloat162*)whi, (__nv_bfloat162*)wlo);
    convert_count_kernel<<<egrid, 256>>>(ei, row, col, cnt, E, flag);
    scan1_kernel<<<nb, 1024>>>(cnt, offs, bsum, N);

    // 1) layer 1 (only needs launch #0's whi/wlo) — 4th launch for ncu window
    tc_gemm_kernel<true><<<ggrid, 512, SMEM_GEMM_BYTES>>>(
        x, nullptr, whi, wlo, b1, h, N);

    // 2) finish CSR build
    scan3_kernel<<<n256, 256>>>(offs, bsum, nb, cnt, cursor, rdeg, N);
    fill_kernel<<<egrid, 256>>>(row, col, cursor, srcs, E);

    // 3) mp 1
    aggregate_kernel<<<wgrid, 256>>>(h, offs, cnt, srcs, rdeg,
                                     (__nv_bfloat162*)ahi, (__nv_bfloat162*)alo, N);

    // 4) layer 2
    tc_gemm_kernel<false><<<ggrid, 512, SMEM_GEMM_BYTES>>>(
        ahi, alo, whi + DIM * DIM, wlo + DIM * DIM, b2, h, N);

    // 5) mp 2
    aggregate_kernel<<<wgrid, 256>>>(h, offs, cnt, srcs, rdeg,
                                     (__nv_bfloat162*)ahi, (__nv_bfloat162*)alo, N);

    // 6) layer 3
    tc_gemm_kernel<false><<<ggrid, 512, SMEM_GEMM_BYTES>>>(
        ahi, alo, whi + 2 * DIM * DIM, wlo + 2 * DIM * DIM, b3, out, N);
}